// round 13
// baseline (speedup 1.0000x reference)
#include <cuda_runtime.h>
#include <cuda_fp16.h>
#include <math.h>
#include <stdint.h>

#define BB   8192
#define SDIM 1024
#define IND  512
#define HID  4096

#define LO_SCALE 2048.0f
#define LO_INV   (1.0f / 2048.0f)

// ---------------- scratch ----------------
__device__ __half g_x0h[(size_t)BB * SDIM], g_x0l[(size_t)BB * SDIM];
__device__ __half g_w1h[SDIM * IND], g_w1l[SDIM * IND];
__device__ __half g_w2h[IND * HID],  g_w2l[IND * HID];
__device__ __half g_w3h[HID * IND],  g_w3l[HID * IND];
__device__ __half g_xhh[(size_t)BB * IND], g_xhl[(size_t)BB * IND];
__device__ __half g_zh[(size_t)BB * HID],  g_zl[(size_t)BB * HID];
__device__ float  g_ent[BB];
__device__ int    g_keff;

// ---------------- helpers ----------------
__device__ __forceinline__ uint32_t smem_u32(const void* p) {
    uint32_t a;
    asm("{ .reg .u64 t; cvta.to.shared.u64 t, %1; cvt.u32.u64 %0, t; }" : "=r"(a) : "l"(p));
    return a;
}
__device__ __forceinline__ void split_sc(float a, __half& h, __half& l) {
    h = __float2half_rn(a);
    l = __float2half_rn((a - __half2float(h)) * LO_SCALE);
}
__device__ __forceinline__ void split2_sc(float a, float b, uint32_t& H, uint32_t& L) {
    __half ha, la, hb, lb;
    split_sc(a, ha, la);
    split_sc(b, hb, lb);
    __half2 Hh = __halves2half2(ha, hb), Ll = __halves2half2(la, lb);
    H = *reinterpret_cast<uint32_t*>(&Hh);
    L = *reinterpret_cast<uint32_t*>(&Ll);
}
__device__ __forceinline__ void ldsm4(uint32_t* r, uint32_t addr) {
    asm volatile("ldmatrix.sync.aligned.m8n8.x4.shared.b16 {%0,%1,%2,%3}, [%4];"
        : "=r"(r[0]), "=r"(r[1]), "=r"(r[2]), "=r"(r[3]) : "r"(addr));
}
__device__ __forceinline__ void ldsm4t(uint32_t* r, uint32_t addr) {
    asm volatile("ldmatrix.sync.aligned.m8n8.x4.trans.shared.b16 {%0,%1,%2,%3}, [%4];"
        : "=r"(r[0]), "=r"(r[1]), "=r"(r[2]), "=r"(r[3]) : "r"(addr));
}
__device__ __forceinline__ void mma16816(float* c, const uint32_t* a, uint32_t b0, uint32_t b1) {
    asm volatile(
        "mma.sync.aligned.m16n8k16.row.col.f32.f16.f16.f32 "
        "{%0,%1,%2,%3}, {%4,%5,%6,%7}, {%8,%9}, {%0,%1,%2,%3};"
        : "+f"(c[0]), "+f"(c[1]), "+f"(c[2]), "+f"(c[3])
        : "r"(a[0]), "r"(a[1]), "r"(a[2]), "r"(a[3]), "r"(b0), "r"(b1));
}
__device__ __forceinline__ void mma16816h(uint32_t* c, const uint32_t* a, uint32_t b0, uint32_t b1) {
    asm volatile(
        "mma.sync.aligned.m16n8k16.row.col.f16.f16.f16.f16 "
        "{%0,%1}, {%2,%3,%4,%5}, {%6,%7}, {%0,%1};"
        : "+r"(c[0]), "+r"(c[1])
        : "r"(a[0]), "r"(a[1]), "r"(a[2]), "r"(a[3]), "r"(b0), "r"(b1));
}
__device__ __forceinline__ void cp_async16(uint32_t dst, const void* src) {
    asm volatile("cp.async.cg.shared.global [%0], [%1], 16;" :: "r"(dst), "l"(src));
}
#define CP_COMMIT() asm volatile("cp.async.commit_group;" ::: "memory")
template <int N>
__device__ __forceinline__ void cp_wait() {
    asm volatile("cp.async.wait_group %0;" :: "n"(N) : "memory");
}

// A chunk [128 m][32 k]: two 64B m-rows per 128B smem row, XOR swizzle (conflict-free).
__device__ __forceinline__ uint32_t offA32(int m, int seg) {
    return (uint32_t)((m >> 1) * 128 + (m & 1) * 64 + (((seg) ^ ((m >> 1) & 3)) << 4));
}
// B chunk [32 k][128 n] halfs, 256B rows
__device__ __forceinline__ uint32_t offB(int k, int ns) {
    return (uint32_t)(k * 256 + (((ns) ^ (k & 7)) << 4));
}

// stage: Ah 0 | Al 8K | Bh 16K | Bl 24K = 32KB per stage, 2 stages
#define STAGE_BYTES 32768
#define DYN_SMEM (2 * STAGE_BYTES + 1024)
#define GTHREADS 128

__device__ __forceinline__ void load_chunk(
    uint32_t st, const __half* __restrict__ Ah_g, const __half* __restrict__ Al_g,
    const __half* __restrict__ Bh_g, const __half* __restrict__ Bl_g,
    int tid, int by, int bx, int c, int N, int K) {
    // A: thread = row (128 threads), 4 segs of 16B each
    const int ra = tid;
    const size_t arow = (size_t)(by * 128 + ra) * K + c * 32;
#pragma unroll
    for (int seg = 0; seg < 4; ++seg) {
        const uint32_t d = offA32(ra, seg);
        cp_async16(st + d,        Ah_g + arow + seg * 8);
        cp_async16(st + 8192 + d, Al_g + arow + seg * 8);
    }
    // B: 32 k-rows x 16 ns units; thread -> (kb = tid>>2, 4 ns units)
    const int kb = tid >> 2, ns0 = (tid & 3) * 4;
    const size_t brow = (size_t)(c * 32 + kb) * N + bx * 128;
#pragma unroll
    for (int j = 0; j < 4; ++j) {
        const int ns = ns0 + j;
        const uint32_t d = offB(kb, ns);
        cp_async16(st + 16384 + d, Bh_g + brow + ns * 8);
        cp_async16(st + 24576 + d, Bl_g + brow + ns * 8);
    }
}

// ---------- fp16x3 HMMA GEMM, CTA 128x128, 4 warps, warp tile 64x64, occ 2 ----------
template <int ACT, bool OUTHALF>
__global__ __launch_bounds__(GTHREADS, 2)
void gemm_m(const __half* __restrict__ Ah_g, const __half* __restrict__ Al_g,
            const __half* __restrict__ Bh_g, const __half* __restrict__ Bl_g,
            const float* __restrict__ bias0, const float* __restrict__ bias1,
            const int* __restrict__ modep,
            float* __restrict__ C, __half* __restrict__ Ch, __half* __restrict__ Cl,
            int N, int K) {
    extern __shared__ char dsm_raw[];
    __shared__ float sBias[128];

    const float* bias = bias0;
    if (modep != nullptr && *modep != 0) bias = bias1;

    char* base = dsm_raw;
    {
        uintptr_t mis = ((uintptr_t)base) & 1023;
        base += (1024 - mis) & 1023;
    }
    const uint32_t SB = smem_u32(base);

    const int tid = threadIdx.x;
    const int lane = tid & 31;
    const int wid = tid >> 5;       // 0..3
    const int wm = wid & 1;         // m offset 64*wm
    const int wn = wid >> 1;        // n offset 64*wn
    const int bx = blockIdx.x, by = blockIdx.y;

    sBias[tid] = bias[bx * 128 + tid];

    float    acc_hh[4][8][4];
    uint32_t acc_mx[4][8][2];
#pragma unroll
    for (int i = 0; i < 4; ++i)
#pragma unroll
        for (int j = 0; j < 8; ++j) {
#pragma unroll
            for (int q = 0; q < 4; ++q) acc_hh[i][j][q] = 0.0f;
            acc_mx[i][j][0] = 0u; acc_mx[i][j][1] = 0u;
        }

    const int NC = K >> 5;

    load_chunk(SB, Ah_g, Al_g, Bh_g, Bl_g, tid, by, bx, 0, N, K);
    CP_COMMIT();

    for (int c = 0; c < NC; ++c) {
        const uint32_t st = SB + (uint32_t)(c & 1) * STAGE_BYTES;
        if (c + 1 < NC) {
            load_chunk(SB + (uint32_t)((c + 1) & 1) * STAGE_BYTES,
                       Ah_g, Al_g, Bh_g, Bl_g, tid, by, bx, c + 1, N, K);
            CP_COMMIT();
            cp_wait<1>();
        } else {
            cp_wait<0>();
        }
        __syncthreads();

        const uint32_t sAh = st, sAl = st + 8192, sBh = st + 16384, sBl = st + 24576;
#pragma unroll
        for (int ks = 0; ks < 2; ++ks) {
            const int arow = wm * 64 + (lane & 15);
            const int ags  = 2 * ks + (lane >> 4);
            const int bk   = ks * 16 + (lane & 15);
            const int bns  = wn * 8 + (lane >> 4);

            uint32_t afh[4][4], bfh[4][4];
#pragma unroll
            for (int mt = 0; mt < 4; ++mt) ldsm4(afh[mt], sAh + offA32(arow + mt * 16, ags));
#pragma unroll
            for (int p = 0; p < 4; ++p)   ldsm4t(bfh[p], sBh + offB(bk, bns + 2 * p));

            // hh -> fp32 acc (32 mma)
#pragma unroll
            for (int mt = 0; mt < 4; ++mt)
#pragma unroll
                for (int nt = 0; nt < 8; ++nt)
                    mma16816(acc_hh[mt][nt], afh[mt],
                             bfh[nt >> 1][(nt & 1) * 2], bfh[nt >> 1][(nt & 1) * 2 + 1]);

            // Ah*Bl -> fp16 acc, two p-halves (bounds liveness)
#pragma unroll
            for (int ph = 0; ph < 2; ++ph) {
                uint32_t bfl[2][4];
#pragma unroll
                for (int p = 0; p < 2; ++p)
                    ldsm4t(bfl[p], sBl + offB(bk, bns + 2 * (2 * ph + p)));
#pragma unroll
                for (int mt = 0; mt < 4; ++mt)
#pragma unroll
                    for (int nt = 4 * ph; nt < 4 * ph + 4; ++nt)
                        mma16816h(acc_mx[mt][nt], afh[mt],
                                  bfl[(nt >> 1) & 1][(nt & 1) * 2],
                                  bfl[(nt >> 1) & 1][(nt & 1) * 2 + 1]);
            }

            // Al*Bh -> fp16 acc, two mt-halves
#pragma unroll
            for (int mh = 0; mh < 2; ++mh) {
                uint32_t afl[2][4];
#pragma unroll
                for (int m2 = 0; m2 < 2; ++m2)
                    ldsm4(afl[m2], sAl + offA32(arow + (2 * mh + m2) * 16, ags));
#pragma unroll
                for (int m2 = 0; m2 < 2; ++m2)
#pragma unroll
                    for (int nt = 0; nt < 8; ++nt)
                        mma16816h(acc_mx[2 * mh + m2][nt], afl[m2],
                                  bfh[nt >> 1][(nt & 1) * 2], bfh[nt >> 1][(nt & 1) * 2 + 1]);
            }
        }
        __syncthreads();
    }

    // ---- epilogue ----
    const int gid = lane >> 2, tig = lane & 3;
#pragma unroll
    for (int mt = 0; mt < 4; ++mt) {
#pragma unroll
        for (int nt = 0; nt < 8; ++nt) {
            const int lcol = wn * 64 + nt * 8 + tig * 2;
            const int col = bx * 128 + lcol;
            const float b0 = sBias[lcol], b1 = sBias[lcol + 1];
            const int m0 = by * 128 + wm * 64 + mt * 16 + gid;
            float2 f01 = __half22float2(*reinterpret_cast<__half2*>(&acc_mx[mt][nt][0]));
            float2 f23 = __half22float2(*reinterpret_cast<__half2*>(&acc_mx[mt][nt][1]));
            float v0 = acc_hh[mt][nt][0] + f01.x * LO_INV + b0;
            float v1 = acc_hh[mt][nt][1] + f01.y * LO_INV + b1;
            float v2 = acc_hh[mt][nt][2] + f23.x * LO_INV + b0;
            float v3 = acc_hh[mt][nt][3] + f23.y * LO_INV + b1;
            if (ACT == 1) {
                v0 = v0 / (1.0f + expf(-v0)); v1 = v1 / (1.0f + expf(-v1));
                v2 = v2 / (1.0f + expf(-v2)); v3 = v3 / (1.0f + expf(-v3));
            }
            if (ACT == 2) {
                v0 = fmaxf(v0, 0.0f); v1 = fmaxf(v1, 0.0f);
                v2 = fmaxf(v2, 0.0f); v3 = fmaxf(v3, 0.0f);
            }
            if (OUTHALF) {
                uint32_t H0, L0, H1, L1;
                split2_sc(v0, v1, H0, L0);
                split2_sc(v2, v3, H1, L1);
                *(uint32_t*)(Ch + (size_t)m0 * N + col)       = H0;
                *(uint32_t*)(Cl + (size_t)m0 * N + col)       = L0;
                *(uint32_t*)(Ch + (size_t)(m0 + 8) * N + col) = H1;
                *(uint32_t*)(Cl + (size_t)(m0 + 8) * N + col) = L1;
            } else {
                float2 a; a.x = v0; a.y = v1;
                float2 b; b.x = v2; b.y = v3;
                *(float2*)(C + (size_t)m0 * N + col)       = a;
                *(float2*)(C + (size_t)(m0 + 8) * N + col) = b;
            }
        }
    }
}

// ---------------- split prep ----------------
__global__ __launch_bounds__(256)
void split_w(const float* __restrict__ s0, const float* __restrict__ s1,
             const int* __restrict__ modep,
             __half* __restrict__ h, __half* __restrict__ l, int n4) {
    const float* s = s0;
    if (modep != nullptr && *modep != 0) s = s1;
    int i = blockIdx.x * 256 + threadIdx.x;
    if (i < n4) {
        float4 f = ((const float4*)s)[i];
        uint2 H, L;
        split2_sc(f.x, f.y, H.x, L.x);
        split2_sc(f.z, f.w, H.y, L.y);
        ((uint2*)h)[i] = H;
        ((uint2*)l)[i] = L;
    }
}

// ---------------- per-row entropy of softmax(h) ----------------
__global__ __launch_bounds__(256)
void entropy_k(const float* __restrict__ h) {
    __shared__ float srow[HID];
    __shared__ float r0[8], r1[8];
    const int row = blockIdx.x, tid = threadIdx.x;
    const float* hr = h + (size_t)row * HID;

    float m = -1e30f;
    for (int i = tid; i < HID; i += 256) { float v = hr[i]; srow[i] = v; m = fmaxf(m, v); }
#pragma unroll
    for (int o = 16; o; o >>= 1) m = fmaxf(m, __shfl_xor_sync(0xffffffffu, m, o));
    if ((tid & 31) == 0) r0[tid >> 5] = m;
    __syncthreads();
    float mm = r0[0];
#pragma unroll
    for (int i = 1; i < 8; ++i) mm = fmaxf(mm, r0[i]);

    float s0 = 0.f, s1 = 0.f;
    for (int i = tid; i < HID; i += 256) {
        float v = srow[i];
        float e = expf(v - mm);
        s0 += e; s1 += v * e;
    }
#pragma unroll
    for (int o = 16; o; o >>= 1) {
        s0 += __shfl_xor_sync(0xffffffffu, s0, o);
        s1 += __shfl_xor_sync(0xffffffffu, s1, o);
    }
    __syncthreads();
    if ((tid & 31) == 0) { r0[tid >> 5] = s0; r1[tid >> 5] = s1; }
    __syncthreads();
    if (tid == 0) {
        float S0 = 0.f, S1 = 0.f;
#pragma unroll
        for (int i = 0; i < 8; ++i) { S0 += r0[i]; S1 += r1[i]; }
        g_ent[row] = mm + logf(S0) - S1 / S0;
    }
}

// ---------------- k_eff ----------------
__global__ __launch_bounds__(256)
void keff_k(const int* __restrict__ kptr) {
    __shared__ float r0[8];
    const int tid = threadIdx.x;
    float s = 0.f;
    for (int i = tid; i < BB; i += 256) s += g_ent[i];
#pragma unroll
    for (int o = 16; o; o >>= 1) s += __shfl_xor_sync(0xffffffffu, s, o);
    if ((tid & 31) == 0) r0[tid >> 5] = s;
    __syncthreads();
    if (tid == 0) {
        float t = 0.f;
#pragma unroll
        for (int i = 0; i < 8; ++i) t += r0[i];
        float mean = t / (float)BB;
        float val = (float)(*kptr) * (1.0f + 0.5f * mean / logf((float)HID));
        int ke = (int)floorf(val);
        if (ke > HID / 2) ke = HID / 2;
        if (ke < 1) ke = 1;
        g_keff = ke;
    }
}

// ---------------- k-WTA radix select ----------------
__global__ __launch_bounds__(256)
void kwta_k(float* __restrict__ z) {
    __shared__ unsigned sv[HID];
    __shared__ int hist[256];
    __shared__ int sk;
    __shared__ unsigned spre;
    const int row = blockIdx.x, tid = threadIdx.x;
    float* zr = z + (size_t)row * HID;

    for (int i = tid; i < HID; i += 256) sv[i] = __float_as_uint(zr[i]);

    int k = g_keff;
    unsigned prefix = 0u;

#pragma unroll
    for (int shift = 24; shift >= 0; shift -= 8) {
        hist[tid] = 0;
        __syncthreads();
        const unsigned himask = (shift == 24) ? 0u : (0xffffffffu << (shift + 8));
        for (int i = tid; i < HID; i += 256) {
            unsigned v = sv[i];
            if ((v & himask) == prefix) atomicAdd(&hist[(v >> shift) & 255], 1);
        }
        __syncthreads();
        if (tid == 0) {
            int cum = 0, b = 255;
            for (;; --b) {
                cum += hist[b];
                if (cum >= k || b == 0) break;
            }
            sk = k - (cum - hist[b]);
            spre = prefix | ((unsigned)b << shift);
        }
        __syncthreads();
        k = sk;
        prefix = spre;
    }

    const float th = __uint_as_float(prefix);
    __half* zh = g_zh + (size_t)row * HID;
    __half* zl = g_zl + (size_t)row * HID;
    for (int i = tid; i < HID; i += 256) {
        float v = __uint_as_float(sv[i]);
        v = (v >= th) ? v : 0.0f;
        zr[i] = v;
        __half hv, lv;
        split_sc(v, hv, lv);
        zh[i] = hv;
        zl[i] = lv;
    }
}

// ---------------- launch ----------------
extern "C" void kernel_launch(void* const* d_in, const int* in_sizes, int n_in,
                              void* d_out, int out_size) {
    const float* x     = (const float*)d_in[0];
    const float* Ws    = (const float*)d_in[1];
    const float* bs    = (const float*)d_in[2];
    const float* Wr    = (const float*)d_in[3];
    const float* br    = (const float*)d_in[4];
    const float* W_enc = (const float*)d_in[5];
    const float* b_enc = (const float*)d_in[6];
    const float* W_dec = (const float*)d_in[7];
    const float* b_dec = (const float*)d_in[8];
    const int*   modep = (const int*)d_in[9];
    const int*   kptr  = (const int*)d_in[10];

    float* recon = (float*)d_out;
    float* z     = recon + (size_t)BB * IND;

    void *x0h, *x0l, *w1h, *w1l, *w2h, *w2l, *w3h, *w3l, *xhh, *xhl, *zh, *zl;
    cudaGetSymbolAddress(&x0h, g_x0h); cudaGetSymbolAddress(&x0l, g_x0l);
    cudaGetSymbolAddress(&w1h, g_w1h); cudaGetSymbolAddress(&w1l, g_w1l);
    cudaGetSymbolAddress(&w2h, g_w2h); cudaGetSymbolAddress(&w2l, g_w2l);
    cudaGetSymbolAddress(&w3h, g_w3h); cudaGetSymbolAddress(&w3l, g_w3l);
    cudaGetSymbolAddress(&xhh, g_xhh); cudaGetSymbolAddress(&xhl, g_xhl);
    cudaGetSymbolAddress(&zh, g_zh);   cudaGetSymbolAddress(&zl, g_zl);

    cudaFuncSetAttribute((const void*)gemm_m<1, true>,
                         cudaFuncAttributeMaxDynamicSharedMemorySize, DYN_SMEM);
    cudaFuncSetAttribute((const void*)gemm_m<2, false>,
                         cudaFuncAttributeMaxDynamicSharedMemorySize, DYN_SMEM);
    cudaFuncSetAttribute((const void*)gemm_m<0, false>,
                         cudaFuncAttributeMaxDynamicSharedMemorySize, DYN_SMEM);

    dim3 blk(256);
    dim3 gblk(GTHREADS);

    split_w<<<((size_t)BB * SDIM / 4 + 255) / 256, blk>>>(x, nullptr, nullptr, (__half*)x0h, (__half*)x0l, BB * SDIM / 4);
    split_w<<<(SDIM * IND / 4 + 255) / 256, blk>>>(Ws, Wr, modep, (__half*)w1h, (__half*)w1l, SDIM * IND / 4);
    split_w<<<(IND * HID / 4 + 255) / 256, blk>>>(W_enc, nullptr, nullptr, (__half*)w2h, (__half*)w2l, IND * HID / 4);
    split_w<<<(HID * IND / 4 + 255) / 256, blk>>>(W_dec, nullptr, nullptr, (__half*)w3h, (__half*)w3l, HID * IND / 4);

    // 1) xh = silu(x @ W_head + b_head) -> split halves
    gemm_m<1, true><<<dim3(IND / 128, BB / 128), gblk, DYN_SMEM>>>(
        (const __half*)x0h, (const __half*)x0l, (const __half*)w1h, (const __half*)w1l,
        bs, br, modep, nullptr, (__half*)xhh, (__half*)xhl, IND, SDIM);

    // 2) h = relu(xh @ W_enc + b_enc) -> z region (fp32)
    gemm_m<2, false><<<dim3(HID / 128, BB / 128), gblk, DYN_SMEM>>>(
        (const __half*)xhh, (const __half*)xhl, (const __half*)w2h, (const __half*)w2l,
        b_enc, nullptr, nullptr, z, nullptr, nullptr, HID, IND);

    // 3) entropy, 4) k_eff, 5) k-WTA in place (+ split halves of z)
    entropy_k<<<BB, blk>>>(z);
    keff_k<<<1, blk>>>(kptr);
    kwta_k<<<BB, blk>>>(z);

    // 6) recon = z_sparse @ W_dec + b_dec
    gemm_m<0, false><<<dim3(IND / 128, BB / 128), gblk, DYN_SMEM>>>(
        (const __half*)zh, (const __half*)zl, (const __half*)w3h, (const __half*)w3l,
        b_dec, nullptr, nullptr, recon, nullptr, nullptr, IND, HID);
}

// round 14
// speedup vs baseline: 1.0846x; 1.0846x over previous
#include <cuda_runtime.h>
#include <cuda_fp16.h>
#include <math.h>
#include <stdint.h>

#define BB   8192
#define SDIM 1024
#define IND  512
#define HID  4096

#define LO_SCALE 2048.0f
#define LO_INV   (1.0f / 2048.0f)

// ---------------- scratch ----------------
__device__ __half g_x0h[(size_t)BB * SDIM], g_x0l[(size_t)BB * SDIM];
__device__ __half g_w1h[SDIM * IND], g_w1l[SDIM * IND];
__device__ __half g_w2h[IND * HID],  g_w2l[IND * HID];
__device__ __half g_w3h[HID * IND],  g_w3l[HID * IND];
__device__ __half g_xhh[(size_t)BB * IND], g_xhl[(size_t)BB * IND];
__device__ __half g_zh[(size_t)BB * HID],  g_zl[(size_t)BB * HID];
__device__ float  g_ent[BB];
__device__ int    g_keff;

// ---------------- helpers ----------------
__device__ __forceinline__ uint32_t smem_u32(const void* p) {
    uint32_t a;
    asm("{ .reg .u64 t; cvta.to.shared.u64 t, %1; cvt.u32.u64 %0, t; }" : "=r"(a) : "l"(p));
    return a;
}
// FMA-pipe exp (no MUFU): e^x = 2^(x*log2e), |rel err| ~2e-7 for x in [-120*ln2, 88]
__device__ __forceinline__ float fexp(float x) {
    float t = fmaxf(x * 1.442695041f, -120.0f);
    t = fminf(t, 120.0f);
    float r = rintf(t);
    float f = t - r;
    float p = 1.5402e-4f;
    p = fmaf(p, f, 1.333558e-3f);
    p = fmaf(p, f, 9.618129e-3f);
    p = fmaf(p, f, 5.550411e-2f);
    p = fmaf(p, f, 2.402265e-1f);
    p = fmaf(p, f, 6.931472e-1f);
    p = fmaf(p, f, 1.0f);
    int i = (int)r;
    return p * __int_as_float((i + 127) << 23);
}
__device__ __forceinline__ void split_sc(float a, __half& h, __half& l) {
    h = __float2half_rn(a);
    l = __float2half_rn((a - __half2float(h)) * LO_SCALE);
}
__device__ __forceinline__ void split2_sc(float a, float b, uint32_t& H, uint32_t& L) {
    __half ha, la, hb, lb;
    split_sc(a, ha, la);
    split_sc(b, hb, lb);
    __half2 Hh = __halves2half2(ha, hb), Ll = __halves2half2(la, lb);
    H = *reinterpret_cast<uint32_t*>(&Hh);
    L = *reinterpret_cast<uint32_t*>(&Ll);
}
__device__ __forceinline__ void ldsm4(uint32_t* r, uint32_t addr) {
    asm volatile("ldmatrix.sync.aligned.m8n8.x4.shared.b16 {%0,%1,%2,%3}, [%4];"
        : "=r"(r[0]), "=r"(r[1]), "=r"(r[2]), "=r"(r[3]) : "r"(addr));
}
__device__ __forceinline__ void ldsm4t(uint32_t* r, uint32_t addr) {
    asm volatile("ldmatrix.sync.aligned.m8n8.x4.trans.shared.b16 {%0,%1,%2,%3}, [%4];"
        : "=r"(r[0]), "=r"(r[1]), "=r"(r[2]), "=r"(r[3]) : "r"(addr));
}
__device__ __forceinline__ void mma16816(float* c, const uint32_t* a, uint32_t b0, uint32_t b1) {
    asm volatile(
        "mma.sync.aligned.m16n8k16.row.col.f32.f16.f16.f32 "
        "{%0,%1,%2,%3}, {%4,%5,%6,%7}, {%8,%9}, {%0,%1,%2,%3};"
        : "+f"(c[0]), "+f"(c[1]), "+f"(c[2]), "+f"(c[3])
        : "r"(a[0]), "r"(a[1]), "r"(a[2]), "r"(a[3]), "r"(b0), "r"(b1));
}
__device__ __forceinline__ void mma16816h(uint32_t* c, const uint32_t* a, uint32_t b0, uint32_t b1) {
    asm volatile(
        "mma.sync.aligned.m16n8k16.row.col.f16.f16.f16.f16 "
        "{%0,%1}, {%2,%3,%4,%5}, {%6,%7}, {%0,%1};"
        : "+r"(c[0]), "+r"(c[1])
        : "r"(a[0]), "r"(a[1]), "r"(a[2]), "r"(a[3]), "r"(b0), "r"(b1));
}
__device__ __forceinline__ void cp_async16(uint32_t dst, const void* src) {
    asm volatile("cp.async.cg.shared.global [%0], [%1], 16;" :: "r"(dst), "l"(src));
}
#define CP_COMMIT() asm volatile("cp.async.commit_group;" ::: "memory")
template <int N>
__device__ __forceinline__ void cp_wait() {
    asm volatile("cp.async.wait_group %0;" :: "n"(N) : "memory");
}

// A chunk [128 m][32 k]: two 64B m-rows per 128B smem row, XOR swizzle (conflict-free).
__device__ __forceinline__ uint32_t offA32(int m, int seg) {
    return (uint32_t)((m >> 1) * 128 + (m & 1) * 64 + (((seg) ^ ((m >> 1) & 3)) << 4));
}
// B chunk [32 k][128 n] halfs, 256B rows
__device__ __forceinline__ uint32_t offB(int k, int ns) {
    return (uint32_t)(k * 256 + (((ns) ^ (k & 7)) << 4));
}

// stage: Ah 0 | Al 8K | Bh 16K | Bl 24K = 32KB per stage, 2 stages
#define STAGE_BYTES 32768
#define DYN_SMEM (2 * STAGE_BYTES + 1024)

__device__ __forceinline__ void load_chunk(
    uint32_t st, const __half* __restrict__ Ah_g, const __half* __restrict__ Al_g,
    const __half* __restrict__ Bh_g, const __half* __restrict__ Bl_g,
    int tid, int by, int bx, int c, int N, int K) {
    const int ra = tid >> 1, sa0 = (tid & 1) * 2;
    const size_t arow = (size_t)(by * 128 + ra) * K + c * 32;
#pragma unroll
    for (int j = 0; j < 2; ++j) {
        const int seg = sa0 + j;
        const uint32_t d = offA32(ra, seg);
        cp_async16(st + d,        Ah_g + arow + seg * 8);
        cp_async16(st + 8192 + d, Al_g + arow + seg * 8);
    }
    const int kb = tid >> 3, ns0 = (tid & 7) * 2;
    const size_t brow = (size_t)(c * 32 + kb) * N + bx * 128;
#pragma unroll
    for (int j = 0; j < 2; ++j) {
        const int ns = ns0 + j;
        const uint32_t d = offB(kb, ns);
        cp_async16(st + 16384 + d, Bh_g + brow + ns * 8);
        cp_async16(st + 24576 + d, Bl_g + brow + ns * 8);
    }
}

// ---------------- fp16x3 HMMA GEMM, CTA 128x128, warp 64x32, occ 2 ----------------
template <int ACT, bool OUTHALF>
__global__ __launch_bounds__(256, 2)
void gemm_m(const __half* __restrict__ Ah_g, const __half* __restrict__ Al_g,
            const __half* __restrict__ Bh_g, const __half* __restrict__ Bl_g,
            const float* __restrict__ bias0, const float* __restrict__ bias1,
            const int* __restrict__ modep,
            float* __restrict__ C, __half* __restrict__ Ch, __half* __restrict__ Cl,
            int N, int K) {
    extern __shared__ char dsm_raw[];
    __shared__ float sBias[128];

    const float* bias = bias0;
    if (modep != nullptr && *modep != 0) bias = bias1;

    char* base = dsm_raw;
    {
        uintptr_t mis = ((uintptr_t)base) & 1023;
        base += (1024 - mis) & 1023;
    }
    const uint32_t SB = smem_u32(base);

    const int tid = threadIdx.x;
    const int lane = tid & 31;
    const int wid = tid >> 5;
    const int wm = wid & 1;
    const int wn = wid >> 1;
    const int bx = blockIdx.x, by = blockIdx.y;

    if (tid < 128) sBias[tid] = bias[bx * 128 + tid];

    float    acc_hh[4][4][4];
    uint32_t acc_mx[4][4][2];
#pragma unroll
    for (int i = 0; i < 4; ++i)
#pragma unroll
        for (int j = 0; j < 4; ++j) {
#pragma unroll
            for (int q = 0; q < 4; ++q) acc_hh[i][j][q] = 0.0f;
            acc_mx[i][j][0] = 0u; acc_mx[i][j][1] = 0u;
        }

    const int NC = K >> 5;

    load_chunk(SB, Ah_g, Al_g, Bh_g, Bl_g, tid, by, bx, 0, N, K);
    CP_COMMIT();

    for (int c = 0; c < NC; ++c) {
        const uint32_t st = SB + (uint32_t)(c & 1) * STAGE_BYTES;
        if (c + 1 < NC) {
            load_chunk(SB + (uint32_t)((c + 1) & 1) * STAGE_BYTES,
                       Ah_g, Al_g, Bh_g, Bl_g, tid, by, bx, c + 1, N, K);
            CP_COMMIT();
            cp_wait<1>();
        } else {
            cp_wait<0>();
        }
        __syncthreads();

        const uint32_t sAh = st, sAl = st + 8192, sBh = st + 16384, sBl = st + 24576;
#pragma unroll
        for (int ks = 0; ks < 2; ++ks) {
            const int arow = wm * 64 + (lane & 15);
            const int ags  = 2 * ks + (lane >> 4);
            const int bk   = ks * 16 + (lane & 15);
            const int bns  = wn * 4 + (lane >> 4);

            uint32_t afh[4][4], bfh[2][4];
#pragma unroll
            for (int mt = 0; mt < 4; ++mt) ldsm4(afh[mt], sAh + offA32(arow + mt * 16, ags));
#pragma unroll
            for (int p = 0; p < 2; ++p)   ldsm4t(bfh[p], sBh + offB(bk, bns + 2 * p));

            // hh -> fp32 acc
#pragma unroll
            for (int mt = 0; mt < 4; ++mt)
#pragma unroll
                for (int nt = 0; nt < 4; ++nt)
                    mma16816(acc_hh[mt][nt], afh[mt],
                             bfh[nt >> 1][(nt & 1) * 2], bfh[nt >> 1][(nt & 1) * 2 + 1]);

            // Ah*Bl -> fp16 acc
            {
                uint32_t bfl[2][4];
#pragma unroll
                for (int p = 0; p < 2; ++p) ldsm4t(bfl[p], sBl + offB(bk, bns + 2 * p));
#pragma unroll
                for (int mt = 0; mt < 4; ++mt)
#pragma unroll
                    for (int nt = 0; nt < 4; ++nt)
                        mma16816h(acc_mx[mt][nt], afh[mt],
                                  bfl[nt >> 1][(nt & 1) * 2], bfl[nt >> 1][(nt & 1) * 2 + 1]);
            }

            // Al*Bh -> fp16 acc (2 mt at a time to bound liveness)
#pragma unroll
            for (int mh = 0; mh < 2; ++mh) {
                uint32_t afl[2][4];
#pragma unroll
                for (int m2 = 0; m2 < 2; ++m2)
                    ldsm4(afl[m2], sAl + offA32(arow + (2 * mh + m2) * 16, ags));
#pragma unroll
                for (int m2 = 0; m2 < 2; ++m2)
#pragma unroll
                    for (int nt = 0; nt < 4; ++nt)
                        mma16816h(acc_mx[2 * mh + m2][nt], afl[m2],
                                  bfh[nt >> 1][(nt & 1) * 2], bfh[nt >> 1][(nt & 1) * 2 + 1]);
            }
        }
        __syncthreads();
    }

    // ---- epilogue ----
    const int gid = lane >> 2, tig = lane & 3;
#pragma unroll
    for (int mt = 0; mt < 4; ++mt) {
#pragma unroll
        for (int nt = 0; nt < 4; ++nt) {
            const int lcol = wn * 32 + nt * 8 + tig * 2;
            const int col = bx * 128 + lcol;
            const float b0 = sBias[lcol], b1 = sBias[lcol + 1];
            const int m0 = by * 128 + wm * 64 + mt * 16 + gid;
            float2 f01 = __half22float2(*reinterpret_cast<__half2*>(&acc_mx[mt][nt][0]));
            float2 f23 = __half22float2(*reinterpret_cast<__half2*>(&acc_mx[mt][nt][1]));
            float v0 = acc_hh[mt][nt][0] + f01.x * LO_INV + b0;
            float v1 = acc_hh[mt][nt][1] + f01.y * LO_INV + b1;
            float v2 = acc_hh[mt][nt][2] + f23.x * LO_INV + b0;
            float v3 = acc_hh[mt][nt][3] + f23.y * LO_INV + b1;
            if (ACT == 1) {
                v0 = v0 / (1.0f + fexp(-v0)); v1 = v1 / (1.0f + fexp(-v1));
                v2 = v2 / (1.0f + fexp(-v2)); v3 = v3 / (1.0f + fexp(-v3));
            }
            if (ACT == 2) {
                v0 = fmaxf(v0, 0.0f); v1 = fmaxf(v1, 0.0f);
                v2 = fmaxf(v2, 0.0f); v3 = fmaxf(v3, 0.0f);
            }
            if (OUTHALF) {
                uint32_t H0, L0, H1, L1;
                split2_sc(v0, v1, H0, L0);
                split2_sc(v2, v3, H1, L1);
                *(uint32_t*)(Ch + (size_t)m0 * N + col)       = H0;
                *(uint32_t*)(Cl + (size_t)m0 * N + col)       = L0;
                *(uint32_t*)(Ch + (size_t)(m0 + 8) * N + col) = H1;
                *(uint32_t*)(Cl + (size_t)(m0 + 8) * N + col) = L1;
            } else {
                float2 a; a.x = v0; a.y = v1;
                float2 b; b.x = v2; b.y = v3;
                *(float2*)(C + (size_t)m0 * N + col)       = a;
                *(float2*)(C + (size_t)(m0 + 8) * N + col) = b;
            }
        }
    }
}

// ---------------- split prep ----------------
__global__ __launch_bounds__(256)
void split_w(const float* __restrict__ s0, const float* __restrict__ s1,
             const int* __restrict__ modep,
             __half* __restrict__ h, __half* __restrict__ l, int n4) {
    const float* s = s0;
    if (modep != nullptr && *modep != 0) s = s1;
    int i = blockIdx.x * 256 + threadIdx.x;
    if (i < n4) {
        float4 f = ((const float4*)s)[i];
        uint2 H, L;
        split2_sc(f.x, f.y, H.x, L.x);
        split2_sc(f.z, f.w, H.y, L.y);
        ((uint2*)h)[i] = H;
        ((uint2*)l)[i] = L;
    }
}

// ---------------- per-row entropy of softmax(h), FMA-pipe exp ----------------
__global__ __launch_bounds__(256)
void entropy_k(const float* __restrict__ h) {
    __shared__ float srow[HID];
    __shared__ float r0[8], r1[8];
    const int row = blockIdx.x, tid = threadIdx.x;
    const float* hr = h + (size_t)row * HID;

    float m = -1e30f;
    for (int i = tid; i < HID; i += 256) { float v = hr[i]; srow[i] = v; m = fmaxf(m, v); }
#pragma unroll
    for (int o = 16; o; o >>= 1) m = fmaxf(m, __shfl_xor_sync(0xffffffffu, m, o));
    if ((tid & 31) == 0) r0[tid >> 5] = m;
    __syncthreads();
    float mm = r0[0];
#pragma unroll
    for (int i = 1; i < 8; ++i) mm = fmaxf(mm, r0[i]);

    float s0 = 0.f, s1 = 0.f;
    for (int i = tid; i < HID; i += 256) {
        float v = srow[i];
        float e = fexp(v - mm);
        s0 += e; s1 += v * e;
    }
#pragma unroll
    for (int o = 16; o; o >>= 1) {
        s0 += __shfl_xor_sync(0xffffffffu, s0, o);
        s1 += __shfl_xor_sync(0xffffffffu, s1, o);
    }
    __syncthreads();
    if ((tid & 31) == 0) { r0[tid >> 5] = s0; r1[tid >> 5] = s1; }
    __syncthreads();
    if (tid == 0) {
        float S0 = 0.f, S1 = 0.f;
#pragma unroll
        for (int i = 0; i < 8; ++i) { S0 += r0[i]; S1 += r1[i]; }
        g_ent[row] = mm + logf(S0) - S1 / S0;
    }
}

// ---------------- k_eff ----------------
__global__ __launch_bounds__(256)
void keff_k(const int* __restrict__ kptr) {
    __shared__ float r0[8];
    const int tid = threadIdx.x;
    float s = 0.f;
    for (int i = tid; i < BB; i += 256) s += g_ent[i];
#pragma unroll
    for (int o = 16; o; o >>= 1) s += __shfl_xor_sync(0xffffffffu, s, o);
    if ((tid & 31) == 0) r0[tid >> 5] = s;
    __syncthreads();
    if (tid == 0) {
        float t = 0.f;
#pragma unroll
        for (int i = 0; i < 8; ++i) t += r0[i];
        float mean = t / (float)BB;
        float val = (float)(*kptr) * (1.0f + 0.5f * mean / logf((float)HID));
        int ke = (int)floorf(val);
        if (ke > HID / 2) ke = HID / 2;
        if (ke < 1) ke = 1;
        g_keff = ke;
    }
}

// ---------------- k-WTA radix select ----------------
__global__ __launch_bounds__(256)
void kwta_k(float* __restrict__ z) {
    __shared__ unsigned sv[HID];
    __shared__ int hist[256];
    __shared__ int sk;
    __shared__ unsigned spre;
    const int row = blockIdx.x, tid = threadIdx.x;
    float* zr = z + (size_t)row * HID;

    for (int i = tid; i < HID; i += 256) sv[i] = __float_as_uint(zr[i]);

    int k = g_keff;
    unsigned prefix = 0u;

#pragma unroll
    for (int shift = 24; shift >= 0; shift -= 8) {
        hist[tid] = 0;
        __syncthreads();
        const unsigned himask = (shift == 24) ? 0u : (0xffffffffu << (shift + 8));
        for (int i = tid; i < HID; i += 256) {
            unsigned v = sv[i];
            if ((v & himask) == prefix) atomicAdd(&hist[(v >> shift) & 255], 1);
        }
        __syncthreads();
        if (tid == 0) {
            int cum = 0, b = 255;
            for (;; --b) {
                cum += hist[b];
                if (cum >= k || b == 0) break;
            }
            sk = k - (cum - hist[b]);
            spre = prefix | ((unsigned)b << shift);
        }
        __syncthreads();
        k = sk;
        prefix = spre;
    }

    const float th = __uint_as_float(prefix);
    __half* zh = g_zh + (size_t)row * HID;
    __half* zl = g_zl + (size_t)row * HID;
    for (int i = tid; i < HID; i += 256) {
        float v = __uint_as_float(sv[i]);
        v = (v >= th) ? v : 0.0f;
        zr[i] = v;
        __half hv, lv;
        split_sc(v, hv, lv);
        zh[i] = hv;
        zl[i] = lv;
    }
}

// ---------------- launch ----------------
extern "C" void kernel_launch(void* const* d_in, const int* in_sizes, int n_in,
                              void* d_out, int out_size) {
    const float* x     = (const float*)d_in[0];
    const float* Ws    = (const float*)d_in[1];
    const float* bs    = (const float*)d_in[2];
    const float* Wr    = (const float*)d_in[3];
    const float* br    = (const float*)d_in[4];
    const float* W_enc = (const float*)d_in[5];
    const float* b_enc = (const float*)d_in[6];
    const float* W_dec = (const float*)d_in[7];
    const float* b_dec = (const float*)d_in[8];
    const int*   modep = (const int*)d_in[9];
    const int*   kptr  = (const int*)d_in[10];

    float* recon = (float*)d_out;
    float* z     = recon + (size_t)BB * IND;

    void *x0h, *x0l, *w1h, *w1l, *w2h, *w2l, *w3h, *w3l, *xhh, *xhl, *zh, *zl;
    cudaGetSymbolAddress(&x0h, g_x0h); cudaGetSymbolAddress(&x0l, g_x0l);
    cudaGetSymbolAddress(&w1h, g_w1h); cudaGetSymbolAddress(&w1l, g_w1l);
    cudaGetSymbolAddress(&w2h, g_w2h); cudaGetSymbolAddress(&w2l, g_w2l);
    cudaGetSymbolAddress(&w3h, g_w3h); cudaGetSymbolAddress(&w3l, g_w3l);
    cudaGetSymbolAddress(&xhh, g_xhh); cudaGetSymbolAddress(&xhl, g_xhl);
    cudaGetSymbolAddress(&zh, g_zh);   cudaGetSymbolAddress(&zl, g_zl);

    cudaFuncSetAttribute((const void*)gemm_m<1, true>,
                         cudaFuncAttributeMaxDynamicSharedMemorySize, DYN_SMEM);
    cudaFuncSetAttribute((const void*)gemm_m<2, false>,
                         cudaFuncAttributeMaxDynamicSharedMemorySize, DYN_SMEM);
    cudaFuncSetAttribute((const void*)gemm_m<0, false>,
                         cudaFuncAttributeMaxDynamicSharedMemorySize, DYN_SMEM);

    dim3 blk(256);

    split_w<<<((size_t)BB * SDIM / 4 + 255) / 256, blk>>>(x, nullptr, nullptr, (__half*)x0h, (__half*)x0l, BB * SDIM / 4);
    split_w<<<(SDIM * IND / 4 + 255) / 256, blk>>>(Ws, Wr, modep, (__half*)w1h, (__half*)w1l, SDIM * IND / 4);
    split_w<<<(IND * HID / 4 + 255) / 256, blk>>>(W_enc, nullptr, nullptr, (__half*)w2h, (__half*)w2l, IND * HID / 4);
    split_w<<<(HID * IND / 4 + 255) / 256, blk>>>(W_dec, nullptr, nullptr, (__half*)w3h, (__half*)w3l, HID * IND / 4);

    // 1) xh = silu(x @ W_head + b_head) -> split halves
    gemm_m<1, true><<<dim3(IND / 128, BB / 128), blk, DYN_SMEM>>>(
        (const __half*)x0h, (const __half*)x0l, (const __half*)w1h, (const __half*)w1l,
        bs, br, modep, nullptr, (__half*)xhh, (__half*)xhl, IND, SDIM);

    // 2) h = relu(xh @ W_enc + b_enc) -> z region (fp32)
    gemm_m<2, false><<<dim3(HID / 128, BB / 128), blk, DYN_SMEM>>>(
        (const __half*)xhh, (const __half*)xhl, (const __half*)w2h, (const __half*)w2l,
        b_enc, nullptr, nullptr, z, nullptr, nullptr, HID, IND);

    // 3) entropy, 4) k_eff, 5) k-WTA in place (+ split halves of z)
    entropy_k<<<BB, blk>>>(z);
    keff_k<<<1, blk>>>(kptr);
    kwta_k<<<BB, blk>>>(z);

    // 6) recon = z_sparse @ W_dec + b_dec
    gemm_m<0, false><<<dim3(IND / 128, BB / 128), blk, DYN_SMEM>>>(
        (const __half*)zh, (const __half*)zl, (const __half*)w3h, (const __half*)w3l,
        b_dec, nullptr, nullptr, recon, nullptr, nullptr, IND, HID);
}

// round 15
// speedup vs baseline: 1.3756x; 1.2684x over previous
#include <cuda_runtime.h>
#include <cuda_fp16.h>
#include <math.h>
#include <stdint.h>

#define BB   8192
#define SDIM 1024
#define IND  512
#define HID  4096

#define LO_SCALE 2048.0f
#define LO_INV   (1.0f / 2048.0f)

// ---------------- scratch ----------------
__device__ __half g_x0h[(size_t)BB * SDIM], g_x0l[(size_t)BB * SDIM];
__device__ __half g_w1h[SDIM * IND], g_w1l[SDIM * IND];
__device__ __half g_w2h[IND * HID],  g_w2l[IND * HID];
__device__ __half g_w3h[HID * IND];                  // GEMM3 single-pass: hi only
__device__ __half g_xhh[(size_t)BB * IND], g_xhl[(size_t)BB * IND];
__device__ __half g_zh[(size_t)BB * HID];            // masked z, fp16 (GEMM3 input)
__device__ float  g_ent[BB];
__device__ int    g_keff;

// ---------------- helpers ----------------
__device__ __forceinline__ uint32_t smem_u32(const void* p) {
    uint32_t a;
    asm("{ .reg .u64 t; cvta.to.shared.u64 t, %1; cvt.u32.u64 %0, t; }" : "=r"(a) : "l"(p));
    return a;
}
__device__ __forceinline__ void split_sc(float a, __half& h, __half& l) {
    h = __float2half_rn(a);
    l = __float2half_rn((a - __half2float(h)) * LO_SCALE);
}
__device__ __forceinline__ void split2_sc(float a, float b, uint32_t& H, uint32_t& L) {
    __half ha, la, hb, lb;
    split_sc(a, ha, la);
    split_sc(b, hb, lb);
    __half2 Hh = __halves2half2(ha, hb), Ll = __halves2half2(la, lb);
    H = *reinterpret_cast<uint32_t*>(&Hh);
    L = *reinterpret_cast<uint32_t*>(&Ll);
}
__device__ __forceinline__ void ldsm4(uint32_t* r, uint32_t addr) {
    asm volatile("ldmatrix.sync.aligned.m8n8.x4.shared.b16 {%0,%1,%2,%3}, [%4];"
        : "=r"(r[0]), "=r"(r[1]), "=r"(r[2]), "=r"(r[3]) : "r"(addr));
}
__device__ __forceinline__ void ldsm4t(uint32_t* r, uint32_t addr) {
    asm volatile("ldmatrix.sync.aligned.m8n8.x4.trans.shared.b16 {%0,%1,%2,%3}, [%4];"
        : "=r"(r[0]), "=r"(r[1]), "=r"(r[2]), "=r"(r[3]) : "r"(addr));
}
__device__ __forceinline__ void mma16816(float* c, const uint32_t* a, uint32_t b0, uint32_t b1) {
    asm volatile(
        "mma.sync.aligned.m16n8k16.row.col.f32.f16.f16.f32 "
        "{%0,%1,%2,%3}, {%4,%5,%6,%7}, {%8,%9}, {%0,%1,%2,%3};"
        : "+f"(c[0]), "+f"(c[1]), "+f"(c[2]), "+f"(c[3])
        : "r"(a[0]), "r"(a[1]), "r"(a[2]), "r"(a[3]), "r"(b0), "r"(b1));
}
__device__ __forceinline__ void mma16816h(uint32_t* c, const uint32_t* a, uint32_t b0, uint32_t b1) {
    asm volatile(
        "mma.sync.aligned.m16n8k16.row.col.f16.f16.f16.f16 "
        "{%0,%1}, {%2,%3,%4,%5}, {%6,%7}, {%0,%1};"
        : "+r"(c[0]), "+r"(c[1])
        : "r"(a[0]), "r"(a[1]), "r"(a[2]), "r"(a[3]), "r"(b0), "r"(b1));
}
__device__ __forceinline__ void cp_async16(uint32_t dst, const void* src) {
    asm volatile("cp.async.cg.shared.global [%0], [%1], 16;" :: "r"(dst), "l"(src));
}
#define CP_COMMIT() asm volatile("cp.async.commit_group;" ::: "memory")
template <int N>
__device__ __forceinline__ void cp_wait() {
    asm volatile("cp.async.wait_group %0;" :: "n"(N) : "memory");
}

// A chunk [128 m][32 k]: two 64B m-rows per 128B smem row, XOR swizzle (conflict-free).
__device__ __forceinline__ uint32_t offA32(int m, int seg) {
    return (uint32_t)((m >> 1) * 128 + (m & 1) * 64 + (((seg) ^ ((m >> 1) & 3)) << 4));
}
// B chunk [32 k][128 n] halfs, 256B rows
__device__ __forceinline__ uint32_t offB(int k, int ns) {
    return (uint32_t)(k * 256 + (((ns) ^ (k & 7)) << 4));
}

// full stage: Ah 0 | Al 8K | Bh 16K | Bl 24K = 32KB; single stage: Ah 0 | Bh 8K = 16KB
#define STAGE_BYTES 32768
#define STAGE_BYTES_S 16384
#define DYN_SMEM (2 * STAGE_BYTES + 1024)

template <bool SINGLE>
__device__ __forceinline__ void load_chunk(
    uint32_t st, const __half* __restrict__ Ah_g, const __half* __restrict__ Al_g,
    const __half* __restrict__ Bh_g, const __half* __restrict__ Bl_g,
    int tid, int by, int bx, int c, int N, int K) {
    const int ra = tid >> 1, sa0 = (tid & 1) * 2;
    const size_t arow = (size_t)(by * 128 + ra) * K + c * 32;
    const uint32_t bhOff = SINGLE ? 8192u : 16384u;
#pragma unroll
    for (int j = 0; j < 2; ++j) {
        const int seg = sa0 + j;
        const uint32_t d = offA32(ra, seg);
        cp_async16(st + d, Ah_g + arow + seg * 8);
        if (!SINGLE) cp_async16(st + 8192 + d, Al_g + arow + seg * 8);
    }
    const int kb = tid >> 3, ns0 = (tid & 7) * 2;
    const size_t brow = (size_t)(c * 32 + kb) * N + bx * 128;
#pragma unroll
    for (int j = 0; j < 2; ++j) {
        const int ns = ns0 + j;
        const uint32_t d = offB(kb, ns);
        cp_async16(st + bhOff + d, Bh_g + brow + ns * 8);
        if (!SINGLE) cp_async16(st + 24576 + d, Bl_g + brow + ns * 8);
    }
}

// ---------------- fp16(x3) HMMA GEMM, CTA 128x128, warp 64x32, occ 2 ----------------
// SINGLE=false: 3-pass fp16x3 (hh fp32-acc, mixed fp16-acc, lo pre-scaled 2048)
// SINGLE=true : 1-pass fp16 (hh only) — for GEMM3 where error is not kWTA-amplified
template <int ACT, bool OUTHALF, bool SINGLE>
__global__ __launch_bounds__(256, 2)
void gemm_m(const __half* __restrict__ Ah_g, const __half* __restrict__ Al_g,
            const __half* __restrict__ Bh_g, const __half* __restrict__ Bl_g,
            const float* __restrict__ bias0, const float* __restrict__ bias1,
            const int* __restrict__ modep,
            float* __restrict__ C, __half* __restrict__ Ch, __half* __restrict__ Cl,
            int N, int K) {
    extern __shared__ char dsm_raw[];
    __shared__ float sBias[128];

    const float* bias = bias0;
    if (modep != nullptr && *modep != 0) bias = bias1;

    char* base = dsm_raw;
    {
        uintptr_t mis = ((uintptr_t)base) & 1023;
        base += (1024 - mis) & 1023;
    }
    const uint32_t SB = smem_u32(base);
    const uint32_t STG = SINGLE ? STAGE_BYTES_S : STAGE_BYTES;

    const int tid = threadIdx.x;
    const int lane = tid & 31;
    const int wid = tid >> 5;
    const int wm = wid & 1;
    const int wn = wid >> 1;
    const int bx = blockIdx.x, by = blockIdx.y;

    if (tid < 128) sBias[tid] = bias[bx * 128 + tid];

    float    acc_hh[4][4][4];
    uint32_t acc_mx[4][4][2];
#pragma unroll
    for (int i = 0; i < 4; ++i)
#pragma unroll
        for (int j = 0; j < 4; ++j) {
#pragma unroll
            for (int q = 0; q < 4; ++q) acc_hh[i][j][q] = 0.0f;
            acc_mx[i][j][0] = 0u; acc_mx[i][j][1] = 0u;
        }

    const int NC = K >> 5;

    load_chunk<SINGLE>(SB, Ah_g, Al_g, Bh_g, Bl_g, tid, by, bx, 0, N, K);
    CP_COMMIT();

    for (int c = 0; c < NC; ++c) {
        const uint32_t st = SB + (uint32_t)(c & 1) * STG;
        if (c + 1 < NC) {
            load_chunk<SINGLE>(SB + (uint32_t)((c + 1) & 1) * STG,
                               Ah_g, Al_g, Bh_g, Bl_g, tid, by, bx, c + 1, N, K);
            CP_COMMIT();
            cp_wait<1>();
        } else {
            cp_wait<0>();
        }
        __syncthreads();

        const uint32_t sAh = st;
        const uint32_t sBh = st + (SINGLE ? 8192 : 16384);
        const uint32_t sAl = st + 8192;       // unused when SINGLE
        const uint32_t sBl = st + 24576;      // unused when SINGLE
#pragma unroll
        for (int ks = 0; ks < 2; ++ks) {
            const int arow = wm * 64 + (lane & 15);
            const int ags  = 2 * ks + (lane >> 4);
            const int bk   = ks * 16 + (lane & 15);
            const int bns  = wn * 4 + (lane >> 4);

            uint32_t afh[4][4], bfh[2][4];
#pragma unroll
            for (int mt = 0; mt < 4; ++mt) ldsm4(afh[mt], sAh + offA32(arow + mt * 16, ags));
#pragma unroll
            for (int p = 0; p < 2; ++p)   ldsm4t(bfh[p], sBh + offB(bk, bns + 2 * p));

            // hh -> fp32 acc
#pragma unroll
            for (int mt = 0; mt < 4; ++mt)
#pragma unroll
                for (int nt = 0; nt < 4; ++nt)
                    mma16816(acc_hh[mt][nt], afh[mt],
                             bfh[nt >> 1][(nt & 1) * 2], bfh[nt >> 1][(nt & 1) * 2 + 1]);

            if (!SINGLE) {
                // Ah*Bl -> fp16 acc
                {
                    uint32_t bfl[2][4];
#pragma unroll
                    for (int p = 0; p < 2; ++p) ldsm4t(bfl[p], sBl + offB(bk, bns + 2 * p));
#pragma unroll
                    for (int mt = 0; mt < 4; ++mt)
#pragma unroll
                        for (int nt = 0; nt < 4; ++nt)
                            mma16816h(acc_mx[mt][nt], afh[mt],
                                      bfl[nt >> 1][(nt & 1) * 2], bfl[nt >> 1][(nt & 1) * 2 + 1]);
                }
                // Al*Bh -> fp16 acc (2 mt at a time to bound liveness)
#pragma unroll
                for (int mh = 0; mh < 2; ++mh) {
                    uint32_t afl[2][4];
#pragma unroll
                    for (int m2 = 0; m2 < 2; ++m2)
                        ldsm4(afl[m2], sAl + offA32(arow + (2 * mh + m2) * 16, ags));
#pragma unroll
                    for (int m2 = 0; m2 < 2; ++m2)
#pragma unroll
                        for (int nt = 0; nt < 4; ++nt)
                            mma16816h(acc_mx[2 * mh + m2][nt], afl[m2],
                                      bfh[nt >> 1][(nt & 1) * 2], bfh[nt >> 1][(nt & 1) * 2 + 1]);
                }
            }
        }
        __syncthreads();
    }

    // ---- epilogue ----
    const int gid = lane >> 2, tig = lane & 3;
#pragma unroll
    for (int mt = 0; mt < 4; ++mt) {
#pragma unroll
        for (int nt = 0; nt < 4; ++nt) {
            const int lcol = wn * 32 + nt * 8 + tig * 2;
            const int col = bx * 128 + lcol;
            const float b0 = sBias[lcol], b1 = sBias[lcol + 1];
            const int m0 = by * 128 + wm * 64 + mt * 16 + gid;
            float v0, v1, v2, v3;
            if (SINGLE) {
                v0 = acc_hh[mt][nt][0] + b0;
                v1 = acc_hh[mt][nt][1] + b1;
                v2 = acc_hh[mt][nt][2] + b0;
                v3 = acc_hh[mt][nt][3] + b1;
            } else {
                float2 f01 = __half22float2(*reinterpret_cast<__half2*>(&acc_mx[mt][nt][0]));
                float2 f23 = __half22float2(*reinterpret_cast<__half2*>(&acc_mx[mt][nt][1]));
                v0 = acc_hh[mt][nt][0] + f01.x * LO_INV + b0;
                v1 = acc_hh[mt][nt][1] + f01.y * LO_INV + b1;
                v2 = acc_hh[mt][nt][2] + f23.x * LO_INV + b0;
                v3 = acc_hh[mt][nt][3] + f23.y * LO_INV + b1;
            }
            if (ACT == 1) {
                v0 = v0 / (1.0f + expf(-v0)); v1 = v1 / (1.0f + expf(-v1));
                v2 = v2 / (1.0f + expf(-v2)); v3 = v3 / (1.0f + expf(-v3));
            }
            if (ACT == 2) {
                v0 = fmaxf(v0, 0.0f); v1 = fmaxf(v1, 0.0f);
                v2 = fmaxf(v2, 0.0f); v3 = fmaxf(v3, 0.0f);
            }
            if (OUTHALF) {
                uint32_t H0, L0, H1, L1;
                split2_sc(v0, v1, H0, L0);
                split2_sc(v2, v3, H1, L1);
                *(uint32_t*)(Ch + (size_t)m0 * N + col)       = H0;
                *(uint32_t*)(Cl + (size_t)m0 * N + col)       = L0;
                *(uint32_t*)(Ch + (size_t)(m0 + 8) * N + col) = H1;
                *(uint32_t*)(Cl + (size_t)(m0 + 8) * N + col) = L1;
            } else {
                float2 a; a.x = v0; a.y = v1;
                float2 b; b.x = v2; b.y = v3;
                *(float2*)(C + (size_t)m0 * N + col)       = a;
                *(float2*)(C + (size_t)(m0 + 8) * N + col) = b;
            }
        }
    }
}

// ---------------- split prep (hi + scaled lo) ----------------
__global__ __launch_bounds__(256)
void split_w(const float* __restrict__ s0, const float* __restrict__ s1,
             const int* __restrict__ modep,
             __half* __restrict__ h, __half* __restrict__ l, int n4) {
    const float* s = s0;
    if (modep != nullptr && *modep != 0) s = s1;
    int i = blockIdx.x * 256 + threadIdx.x;
    if (i < n4) {
        float4 f = ((const float4*)s)[i];
        uint2 H, L;
        split2_sc(f.x, f.y, H.x, L.x);
        split2_sc(f.z, f.w, H.y, L.y);
        ((uint2*)h)[i] = H;
        ((uint2*)l)[i] = L;
    }
}

// ---------------- round prep (hi only, for W_dec) ----------------
__global__ __launch_bounds__(256)
void round_w(const float* __restrict__ s, __half* __restrict__ h, int n4) {
    int i = blockIdx.x * 256 + threadIdx.x;
    if (i < n4) {
        float4 f = ((const float4*)s)[i];
        __half2 a = __floats2half2_rn(f.x, f.y);
        __half2 b = __floats2half2_rn(f.z, f.w);
        uint2 H;
        H.x = *reinterpret_cast<uint32_t*>(&a);
        H.y = *reinterpret_cast<uint32_t*>(&b);
        ((uint2*)h)[i] = H;
    }
}

// ---------------- per-row entropy of softmax(h) ----------------
__global__ __launch_bounds__(256)
void entropy_k(const float* __restrict__ h) {
    __shared__ float srow[HID];
    __shared__ float r0[8], r1[8];
    const int row = blockIdx.x, tid = threadIdx.x;
    const float* hr = h + (size_t)row * HID;

    float m = -1e30f;
    for (int i = tid; i < HID; i += 256) { float v = hr[i]; srow[i] = v; m = fmaxf(m, v); }
#pragma unroll
    for (int o = 16; o; o >>= 1) m = fmaxf(m, __shfl_xor_sync(0xffffffffu, m, o));
    if ((tid & 31) == 0) r0[tid >> 5] = m;
    __syncthreads();
    float mm = r0[0];
#pragma unroll
    for (int i = 1; i < 8; ++i) mm = fmaxf(mm, r0[i]);

    float s0 = 0.f, s1 = 0.f;
    for (int i = tid; i < HID; i += 256) {
        float v = srow[i];
        float e = expf(v - mm);
        s0 += e; s1 += v * e;
    }
#pragma unroll
    for (int o = 16; o; o >>= 1) {
        s0 += __shfl_xor_sync(0xffffffffu, s0, o);
        s1 += __shfl_xor_sync(0xffffffffu, s1, o);
    }
    __syncthreads();
    if ((tid & 31) == 0) { r0[tid >> 5] = s0; r1[tid >> 5] = s1; }
    __syncthreads();
    if (tid == 0) {
        float S0 = 0.f, S1 = 0.f;
#pragma unroll
        for (int i = 0; i < 8; ++i) { S0 += r0[i]; S1 += r1[i]; }
        g_ent[row] = mm + logf(S0) - S1 / S0;
    }
}

// ---------------- k_eff ----------------
__global__ __launch_bounds__(256)
void keff_k(const int* __restrict__ kptr) {
    __shared__ float r0[8];
    const int tid = threadIdx.x;
    float s = 0.f;
    for (int i = tid; i < BB; i += 256) s += g_ent[i];
#pragma unroll
    for (int o = 16; o; o >>= 1) s += __shfl_xor_sync(0xffffffffu, s, o);
    if ((tid & 31) == 0) r0[tid >> 5] = s;
    __syncthreads();
    if (tid == 0) {
        float t = 0.f;
#pragma unroll
        for (int i = 0; i < 8; ++i) t += r0[i];
        float mean = t / (float)BB;
        float val = (float)(*kptr) * (1.0f + 0.5f * mean / logf((float)HID));
        int ke = (int)floorf(val);
        if (ke > HID / 2) ke = HID / 2;
        if (ke < 1) ke = 1;
        g_keff = ke;
    }
}

// ---------------- k-WTA radix select; masks z in place + fp16 copy ----------------
__global__ __launch_bounds__(256)
void kwta_k(float* __restrict__ z) {
    __shared__ unsigned sv[HID];
    __shared__ int hist[256];
    __shared__ int sk;
    __shared__ unsigned spre;
    const int row = blockIdx.x, tid = threadIdx.x;
    float* zr = z + (size_t)row * HID;

    for (int i = tid; i < HID; i += 256) sv[i] = __float_as_uint(zr[i]);

    int k = g_keff;
    unsigned prefix = 0u;

#pragma unroll
    for (int shift = 24; shift >= 0; shift -= 8) {
        hist[tid] = 0;
        __syncthreads();
        const unsigned himask = (shift == 24) ? 0u : (0xffffffffu << (shift + 8));
        for (int i = tid; i < HID; i += 256) {
            unsigned v = sv[i];
            if ((v & himask) == prefix) atomicAdd(&hist[(v >> shift) & 255], 1);
        }
        __syncthreads();
        if (tid == 0) {
            int cum = 0, b = 255;
            for (;; --b) {
                cum += hist[b];
                if (cum >= k || b == 0) break;
            }
            sk = k - (cum - hist[b]);
            spre = prefix | ((unsigned)b << shift);
        }
        __syncthreads();
        k = sk;
        prefix = spre;
    }

    const float th = __uint_as_float(prefix);
    __half* zh = g_zh + (size_t)row * HID;
    for (int i = tid; i < HID; i += 256) {
        float v = __uint_as_float(sv[i]);
        v = (v >= th) ? v : 0.0f;
        zr[i] = v;
        zh[i] = __float2half_rn(v);
    }
}

// ---------------- launch ----------------
extern "C" void kernel_launch(void* const* d_in, const int* in_sizes, int n_in,
                              void* d_out, int out_size) {
    const float* x     = (const float*)d_in[0];
    const float* Ws    = (const float*)d_in[1];
    const float* bs    = (const float*)d_in[2];
    const float* Wr    = (const float*)d_in[3];
    const float* br    = (const float*)d_in[4];
    const float* W_enc = (const float*)d_in[5];
    const float* b_enc = (const float*)d_in[6];
    const float* W_dec = (const float*)d_in[7];
    const float* b_dec = (const float*)d_in[8];
    const int*   modep = (const int*)d_in[9];
    const int*   kptr  = (const int*)d_in[10];

    float* recon = (float*)d_out;
    float* z     = recon + (size_t)BB * IND;

    void *x0h, *x0l, *w1h, *w1l, *w2h, *w2l, *w3h, *xhh, *xhl, *zh;
    cudaGetSymbolAddress(&x0h, g_x0h); cudaGetSymbolAddress(&x0l, g_x0l);
    cudaGetSymbolAddress(&w1h, g_w1h); cudaGetSymbolAddress(&w1l, g_w1l);
    cudaGetSymbolAddress(&w2h, g_w2h); cudaGetSymbolAddress(&w2l, g_w2l);
    cudaGetSymbolAddress(&w3h, g_w3h);
    cudaGetSymbolAddress(&xhh, g_xhh); cudaGetSymbolAddress(&xhl, g_xhl);
    cudaGetSymbolAddress(&zh, g_zh);

    cudaFuncSetAttribute((const void*)gemm_m<1, true, false>,
                         cudaFuncAttributeMaxDynamicSharedMemorySize, DYN_SMEM);
    cudaFuncSetAttribute((const void*)gemm_m<2, false, false>,
                         cudaFuncAttributeMaxDynamicSharedMemorySize, DYN_SMEM);
    cudaFuncSetAttribute((const void*)gemm_m<0, false, true>,
                         cudaFuncAttributeMaxDynamicSharedMemorySize, DYN_SMEM);

    dim3 blk(256);

    split_w<<<((size_t)BB * SDIM / 4 + 255) / 256, blk>>>(x, nullptr, nullptr, (__half*)x0h, (__half*)x0l, BB * SDIM / 4);
    split_w<<<(SDIM * IND / 4 + 255) / 256, blk>>>(Ws, Wr, modep, (__half*)w1h, (__half*)w1l, SDIM * IND / 4);
    split_w<<<(IND * HID / 4 + 255) / 256, blk>>>(W_enc, nullptr, nullptr, (__half*)w2h, (__half*)w2l, IND * HID / 4);
    round_w<<<(HID * IND / 4 + 255) / 256, blk>>>(W_dec, (__half*)w3h, HID * IND / 4);

    // 1) xh = silu(x @ W_head + b_head) -> split halves   [fp16x3]
    gemm_m<1, true, false><<<dim3(IND / 128, BB / 128), blk, DYN_SMEM>>>(
        (const __half*)x0h, (const __half*)x0l, (const __half*)w1h, (const __half*)w1l,
        bs, br, modep, nullptr, (__half*)xhh, (__half*)xhl, IND, SDIM);

    // 2) h = relu(xh @ W_enc + b_enc) -> z region (fp32)  [fp16x3]
    gemm_m<2, false, false><<<dim3(HID / 128, BB / 128), blk, DYN_SMEM>>>(
        (const __half*)xhh, (const __half*)xhl, (const __half*)w2h, (const __half*)w2l,
        b_enc, nullptr, nullptr, z, nullptr, nullptr, HID, IND);

    // 3) entropy, 4) k_eff, 5) k-WTA in place (+ fp16 copy of z)
    entropy_k<<<BB, blk>>>(z);
    keff_k<<<1, blk>>>(kptr);
    kwta_k<<<BB, blk>>>(z);

    // 6) recon = z_sparse @ W_dec + b_dec   [single-pass fp16 — error not amplified]
    gemm_m<0, false, true><<<dim3(IND / 128, BB / 128), blk, DYN_SMEM>>>(
        (const __half*)zh, nullptr, (const __half*)w3h, nullptr,
        b_dec, nullptr, nullptr, recon, nullptr, nullptr, IND, HID);
}

// round 16
// speedup vs baseline: 1.4554x; 1.0580x over previous
#include <cuda_runtime.h>
#include <cuda_fp16.h>
#include <math.h>
#include <stdint.h>

#define BB   8192
#define SDIM 1024
#define IND  512
#define HID  4096

#define LO_SCALE 2048.0f
#define LO_INV   (1.0f / 2048.0f)

// ---------------- scratch ----------------
__device__ __half g_x0h[(size_t)BB * SDIM], g_x0l[(size_t)BB * SDIM];
__device__ __half g_w1h[SDIM * IND], g_w1l[SDIM * IND];
__device__ __half g_w2h[IND * HID],  g_w2l[IND * HID];
__device__ __half g_w3h[HID * IND];
__device__ __half g_xhh[(size_t)BB * IND], g_xhl[(size_t)BB * IND];
__device__ __half g_zh[(size_t)BB * HID];
__device__ float  g_pS0[(size_t)BB * 32];    // per-(row, bx) entropy partials
__device__ float  g_pS1[(size_t)BB * 32];
__device__ float  g_ent[BB];
__device__ int    g_keff;

// ---------------- helpers ----------------
__device__ __forceinline__ uint32_t smem_u32(const void* p) {
    uint32_t a;
    asm("{ .reg .u64 t; cvta.to.shared.u64 t, %1; cvt.u32.u64 %0, t; }" : "=r"(a) : "l"(p));
    return a;
}
// FMA-pipe exp: e^x = 2^(x*log2e), |rel err| ~2e-7
__device__ __forceinline__ float fexp(float x) {
    float t = fmaxf(x * 1.442695041f, -120.0f);
    t = fminf(t, 120.0f);
    float r = rintf(t);
    float f = t - r;
    float p = 1.5402e-4f;
    p = fmaf(p, f, 1.333558e-3f);
    p = fmaf(p, f, 9.618129e-3f);
    p = fmaf(p, f, 5.550411e-2f);
    p = fmaf(p, f, 2.402265e-1f);
    p = fmaf(p, f, 6.931472e-1f);
    p = fmaf(p, f, 1.0f);
    int i = (int)r;
    return p * __int_as_float((i + 127) << 23);
}
__device__ __forceinline__ void split_sc(float a, __half& h, __half& l) {
    h = __float2half_rn(a);
    l = __float2half_rn((a - __half2float(h)) * LO_SCALE);
}
__device__ __forceinline__ void split2_sc(float a, float b, uint32_t& H, uint32_t& L) {
    __half ha, la, hb, lb;
    split_sc(a, ha, la);
    split_sc(b, hb, lb);
    __half2 Hh = __halves2half2(ha, hb), Ll = __halves2half2(la, lb);
    H = *reinterpret_cast<uint32_t*>(&Hh);
    L = *reinterpret_cast<uint32_t*>(&Ll);
}
__device__ __forceinline__ void ldsm4(uint32_t* r, uint32_t addr) {
    asm volatile("ldmatrix.sync.aligned.m8n8.x4.shared.b16 {%0,%1,%2,%3}, [%4];"
        : "=r"(r[0]), "=r"(r[1]), "=r"(r[2]), "=r"(r[3]) : "r"(addr));
}
__device__ __forceinline__ void ldsm4t(uint32_t* r, uint32_t addr) {
    asm volatile("ldmatrix.sync.aligned.m8n8.x4.trans.shared.b16 {%0,%1,%2,%3}, [%4];"
        : "=r"(r[0]), "=r"(r[1]), "=r"(r[2]), "=r"(r[3]) : "r"(addr));
}
__device__ __forceinline__ void mma16816(float* c, const uint32_t* a, uint32_t b0, uint32_t b1) {
    asm volatile(
        "mma.sync.aligned.m16n8k16.row.col.f32.f16.f16.f32 "
        "{%0,%1,%2,%3}, {%4,%5,%6,%7}, {%8,%9}, {%0,%1,%2,%3};"
        : "+f"(c[0]), "+f"(c[1]), "+f"(c[2]), "+f"(c[3])
        : "r"(a[0]), "r"(a[1]), "r"(a[2]), "r"(a[3]), "r"(b0), "r"(b1));
}
__device__ __forceinline__ void mma16816h(uint32_t* c, const uint32_t* a, uint32_t b0, uint32_t b1) {
    asm volatile(
        "mma.sync.aligned.m16n8k16.row.col.f16.f16.f16.f16 "
        "{%0,%1}, {%2,%3,%4,%5}, {%6,%7}, {%0,%1};"
        : "+r"(c[0]), "+r"(c[1])
        : "r"(a[0]), "r"(a[1]), "r"(a[2]), "r"(a[3]), "r"(b0), "r"(b1));
}
__device__ __forceinline__ void cp_async16(uint32_t dst, const void* src) {
    asm volatile("cp.async.cg.shared.global [%0], [%1], 16;" :: "r"(dst), "l"(src));
}
#define CP_COMMIT() asm volatile("cp.async.commit_group;" ::: "memory")
template <int N>
__device__ __forceinline__ void cp_wait() {
    asm volatile("cp.async.wait_group %0;" :: "n"(N) : "memory");
}

// A chunk [128 m][32 k]: two 64B m-rows per 128B smem row, XOR swizzle (conflict-free).
__device__ __forceinline__ uint32_t offA32(int m, int seg) {
    return (uint32_t)((m >> 1) * 128 + (m & 1) * 64 + (((seg) ^ ((m >> 1) & 3)) << 4));
}
// B chunk [32 k][128 n] halfs, 256B rows
__device__ __forceinline__ uint32_t offB(int k, int ns) {
    return (uint32_t)(k * 256 + (((ns) ^ (k & 7)) << 4));
}

#define STAGE_BYTES 32768
#define STAGE_BYTES_S 16384
#define DYN_SMEM (2 * STAGE_BYTES + 1024)

template <bool SINGLE>
__device__ __forceinline__ void load_chunk(
    uint32_t st, const __half* __restrict__ Ah_g, const __half* __restrict__ Al_g,
    const __half* __restrict__ Bh_g, const __half* __restrict__ Bl_g,
    int tid, int by, int bx, int c, int N, int K) {
    const int ra = tid >> 1, sa0 = (tid & 1) * 2;
    const size_t arow = (size_t)(by * 128 + ra) * K + c * 32;
    const uint32_t bhOff = SINGLE ? 8192u : 16384u;
#pragma unroll
    for (int j = 0; j < 2; ++j) {
        const int seg = sa0 + j;
        const uint32_t d = offA32(ra, seg);
        cp_async16(st + d, Ah_g + arow + seg * 8);
        if (!SINGLE) cp_async16(st + 8192 + d, Al_g + arow + seg * 8);
    }
    const int kb = tid >> 3, ns0 = (tid & 7) * 2;
    const size_t brow = (size_t)(c * 32 + kb) * N + bx * 128;
#pragma unroll
    for (int j = 0; j < 2; ++j) {
        const int ns = ns0 + j;
        const uint32_t d = offB(kb, ns);
        cp_async16(st + bhOff + d, Bh_g + brow + ns * 8);
        if (!SINGLE) cp_async16(st + 24576 + d, Bl_g + brow + ns * 8);
    }
}

// ---------------- fp16(x3) HMMA GEMM, CTA 128x128, warp 64x32, occ 2 ----------------
// ENT: fused per-row entropy partials (valid for ACT==2; h>=0 so no-max logsumexp is safe)
template <int ACT, bool OUTHALF, bool SINGLE, bool ENT>
__global__ __launch_bounds__(256, 2)
void gemm_m(const __half* __restrict__ Ah_g, const __half* __restrict__ Al_g,
            const __half* __restrict__ Bh_g, const __half* __restrict__ Bl_g,
            const float* __restrict__ bias0, const float* __restrict__ bias1,
            const int* __restrict__ modep,
            float* __restrict__ C, __half* __restrict__ Ch, __half* __restrict__ Cl,
            float* __restrict__ pS0, float* __restrict__ pS1,
            int N, int K) {
    extern __shared__ char dsm_raw[];
    __shared__ float sBias[128];
    __shared__ float sS0[128], sS1[128];

    const float* bias = bias0;
    if (modep != nullptr && *modep != 0) bias = bias1;

    char* base = dsm_raw;
    {
        uintptr_t mis = ((uintptr_t)base) & 1023;
        base += (1024 - mis) & 1023;
    }
    const uint32_t SB = smem_u32(base);
    const uint32_t STG = SINGLE ? STAGE_BYTES_S : STAGE_BYTES;

    const int tid = threadIdx.x;
    const int lane = tid & 31;
    const int wid = tid >> 5;
    const int wm = wid & 1;
    const int wn = wid >> 1;
    const int bx = blockIdx.x, by = blockIdx.y;

    if (tid < 128) {
        sBias[tid] = bias[bx * 128 + tid];
        if (ENT) { sS0[tid] = 0.0f; sS1[tid] = 0.0f; }
    }

    float    acc_hh[4][4][4];
    uint32_t acc_mx[4][4][2];
#pragma unroll
    for (int i = 0; i < 4; ++i)
#pragma unroll
        for (int j = 0; j < 4; ++j) {
#pragma unroll
            for (int q = 0; q < 4; ++q) acc_hh[i][j][q] = 0.0f;
            acc_mx[i][j][0] = 0u; acc_mx[i][j][1] = 0u;
        }

    const int NC = K >> 5;

    load_chunk<SINGLE>(SB, Ah_g, Al_g, Bh_g, Bl_g, tid, by, bx, 0, N, K);
    CP_COMMIT();

    for (int c = 0; c < NC; ++c) {
        const uint32_t st = SB + (uint32_t)(c & 1) * STG;
        if (c + 1 < NC) {
            load_chunk<SINGLE>(SB + (uint32_t)((c + 1) & 1) * STG,
                               Ah_g, Al_g, Bh_g, Bl_g, tid, by, bx, c + 1, N, K);
            CP_COMMIT();
            cp_wait<1>();
        } else {
            cp_wait<0>();
        }
        __syncthreads();

        const uint32_t sAh = st;
        const uint32_t sBh = st + (SINGLE ? 8192 : 16384);
        const uint32_t sAl = st + 8192;
        const uint32_t sBl = st + 24576;
#pragma unroll
        for (int ks = 0; ks < 2; ++ks) {
            const int arow = wm * 64 + (lane & 15);
            const int ags  = 2 * ks + (lane >> 4);
            const int bk   = ks * 16 + (lane & 15);
            const int bns  = wn * 4 + (lane >> 4);

            uint32_t afh[4][4], bfh[2][4];
#pragma unroll
            for (int mt = 0; mt < 4; ++mt) ldsm4(afh[mt], sAh + offA32(arow + mt * 16, ags));
#pragma unroll
            for (int p = 0; p < 2; ++p)   ldsm4t(bfh[p], sBh + offB(bk, bns + 2 * p));

#pragma unroll
            for (int mt = 0; mt < 4; ++mt)
#pragma unroll
                for (int nt = 0; nt < 4; ++nt)
                    mma16816(acc_hh[mt][nt], afh[mt],
                             bfh[nt >> 1][(nt & 1) * 2], bfh[nt >> 1][(nt & 1) * 2 + 1]);

            if (!SINGLE) {
                {
                    uint32_t bfl[2][4];
#pragma unroll
                    for (int p = 0; p < 2; ++p) ldsm4t(bfl[p], sBl + offB(bk, bns + 2 * p));
#pragma unroll
                    for (int mt = 0; mt < 4; ++mt)
#pragma unroll
                        for (int nt = 0; nt < 4; ++nt)
                            mma16816h(acc_mx[mt][nt], afh[mt],
                                      bfl[nt >> 1][(nt & 1) * 2], bfl[nt >> 1][(nt & 1) * 2 + 1]);
                }
#pragma unroll
                for (int mh = 0; mh < 2; ++mh) {
                    uint32_t afl[2][4];
#pragma unroll
                    for (int m2 = 0; m2 < 2; ++m2)
                        ldsm4(afl[m2], sAl + offA32(arow + (2 * mh + m2) * 16, ags));
#pragma unroll
                    for (int m2 = 0; m2 < 2; ++m2)
#pragma unroll
                        for (int nt = 0; nt < 4; ++nt)
                            mma16816h(acc_mx[2 * mh + m2][nt], afl[m2],
                                      bfh[nt >> 1][(nt & 1) * 2], bfh[nt >> 1][(nt & 1) * 2 + 1]);
                }
            }
        }
        __syncthreads();
    }

    // ---- epilogue ----
    const int gid = lane >> 2, tig = lane & 3;
#pragma unroll
    for (int mt = 0; mt < 4; ++mt) {
        float s0a = 0.f, s1a = 0.f, s0b = 0.f, s1b = 0.f;   // entropy partials rows m0, m0+8
#pragma unroll
        for (int nt = 0; nt < 4; ++nt) {
            const int lcol = wn * 32 + nt * 8 + tig * 2;
            const int col = bx * 128 + lcol;
            const float b0 = sBias[lcol], b1 = sBias[lcol + 1];
            const int m0 = by * 128 + wm * 64 + mt * 16 + gid;
            float v0, v1, v2, v3;
            if (SINGLE) {
                v0 = acc_hh[mt][nt][0] + b0;
                v1 = acc_hh[mt][nt][1] + b1;
                v2 = acc_hh[mt][nt][2] + b0;
                v3 = acc_hh[mt][nt][3] + b1;
            } else {
                float2 f01 = __half22float2(*reinterpret_cast<__half2*>(&acc_mx[mt][nt][0]));
                float2 f23 = __half22float2(*reinterpret_cast<__half2*>(&acc_mx[mt][nt][1]));
                v0 = acc_hh[mt][nt][0] + f01.x * LO_INV + b0;
                v1 = acc_hh[mt][nt][1] + f01.y * LO_INV + b1;
                v2 = acc_hh[mt][nt][2] + f23.x * LO_INV + b0;
                v3 = acc_hh[mt][nt][3] + f23.y * LO_INV + b1;
            }
            if (ACT == 1) {
                v0 = v0 / (1.0f + expf(-v0)); v1 = v1 / (1.0f + expf(-v1));
                v2 = v2 / (1.0f + expf(-v2)); v3 = v3 / (1.0f + expf(-v3));
            }
            if (ACT == 2) {
                v0 = fmaxf(v0, 0.0f); v1 = fmaxf(v1, 0.0f);
                v2 = fmaxf(v2, 0.0f); v3 = fmaxf(v3, 0.0f);
            }
            if (ENT) {
                float e0 = fexp(v0), e1 = fexp(v1), e2 = fexp(v2), e3 = fexp(v3);
                s0a += e0 + e1; s1a += v0 * e0 + v1 * e1;
                s0b += e2 + e3; s1b += v2 * e2 + v3 * e3;
            }
            if (OUTHALF) {
                uint32_t H0, L0, H1, L1;
                split2_sc(v0, v1, H0, L0);
                split2_sc(v2, v3, H1, L1);
                *(uint32_t*)(Ch + (size_t)m0 * N + col)       = H0;
                *(uint32_t*)(Cl + (size_t)m0 * N + col)       = L0;
                *(uint32_t*)(Ch + (size_t)(m0 + 8) * N + col) = H1;
                *(uint32_t*)(Cl + (size_t)(m0 + 8) * N + col) = L1;
            } else {
                float2 a; a.x = v0; a.y = v1;
                float2 b; b.x = v2; b.y = v3;
                *(float2*)(C + (size_t)m0 * N + col)       = a;
                *(float2*)(C + (size_t)(m0 + 8) * N + col) = b;
            }
        }
        if (ENT) {
            // reduce over the 4 tig lanes (same gid)
#pragma unroll
            for (int o = 1; o <= 2; o <<= 1) {
                s0a += __shfl_xor_sync(0xffffffffu, s0a, o);
                s1a += __shfl_xor_sync(0xffffffffu, s1a, o);
                s0b += __shfl_xor_sync(0xffffffffu, s0b, o);
                s1b += __shfl_xor_sync(0xffffffffu, s1b, o);
            }
            if (tig == 0) {
                const int rl = wm * 64 + mt * 16 + gid;
                atomicAdd(&sS0[rl], s0a);
                atomicAdd(&sS1[rl], s1a);
                atomicAdd(&sS0[rl + 8], s0b);
                atomicAdd(&sS1[rl + 8], s1b);
            }
        }
    }
    if (ENT) {
        __syncthreads();
        if (tid < 128) {
            const size_t m = (size_t)(by * 128 + tid);
            pS0[m * 32 + bx] = sS0[tid];
            pS1[m * 32 + bx] = sS1[tid];
        }
    }
}

// ---------------- split prep ----------------
__global__ __launch_bounds__(256)
void split_w(const float* __restrict__ s0, const float* __restrict__ s1,
             const int* __restrict__ modep,
             __half* __restrict__ h, __half* __restrict__ l, int n4) {
    const float* s = s0;
    if (modep != nullptr && *modep != 0) s = s1;
    int i = blockIdx.x * 256 + threadIdx.x;
    if (i < n4) {
        float4 f = ((const float4*)s)[i];
        uint2 H, L;
        split2_sc(f.x, f.y, H.x, L.x);
        split2_sc(f.z, f.w, H.y, L.y);
        ((uint2*)h)[i] = H;
        ((uint2*)l)[i] = L;
    }
}

// ---------------- round prep (hi only, for W_dec) ----------------
__global__ __launch_bounds__(256)
void round_w(const float* __restrict__ s, __half* __restrict__ h, int n4) {
    int i = blockIdx.x * 256 + threadIdx.x;
    if (i < n4) {
        float4 f = ((const float4*)s)[i];
        __half2 a = __floats2half2_rn(f.x, f.y);
        __half2 b = __floats2half2_rn(f.z, f.w);
        uint2 H;
        H.x = *reinterpret_cast<uint32_t*>(&a);
        H.y = *reinterpret_cast<uint32_t*>(&b);
        ((uint2*)h)[i] = H;
    }
}

// ---------------- entropy finish: fold 32 partials per row ----------------
__global__ __launch_bounds__(256)
void entfin_k() {
    const int row = blockIdx.x * 256 + threadIdx.x;
    if (row < BB) {
        const float4* p0 = (const float4*)&g_pS0[(size_t)row * 32];
        const float4* p1 = (const float4*)&g_pS1[(size_t)row * 32];
        float S0 = 0.f, S1 = 0.f;
#pragma unroll
        for (int i = 0; i < 8; ++i) {
            float4 a = p0[i], b = p1[i];
            S0 += (a.x + a.y) + (a.z + a.w);
            S1 += (b.x + b.y) + (b.z + b.w);
        }
        g_ent[row] = logf(S0) - S1 / S0;
    }
}

// ---------------- k_eff ----------------
__global__ __launch_bounds__(256)
void keff_k(const int* __restrict__ kptr) {
    __shared__ float r0[8];
    const int tid = threadIdx.x;
    float s = 0.f;
    for (int i = tid; i < BB; i += 256) s += g_ent[i];
#pragma unroll
    for (int o = 16; o; o >>= 1) s += __shfl_xor_sync(0xffffffffu, s, o);
    if ((tid & 31) == 0) r0[tid >> 5] = s;
    __syncthreads();
    if (tid == 0) {
        float t = 0.f;
#pragma unroll
        for (int i = 0; i < 8; ++i) t += r0[i];
        float mean = t / (float)BB;
        float val = (float)(*kptr) * (1.0f + 0.5f * mean / logf((float)HID));
        int ke = (int)floorf(val);
        if (ke > HID / 2) ke = HID / 2;
        if (ke < 1) ke = 1;
        g_keff = ke;
    }
}

// ---------------- k-WTA radix select; masks z in place + fp16 copy ----------------
__global__ __launch_bounds__(256)
void kwta_k(float* __restrict__ z) {
    __shared__ unsigned sv[HID];
    __shared__ int hist[256];
    __shared__ int sk;
    __shared__ unsigned spre;
    const int row = blockIdx.x, tid = threadIdx.x;
    float* zr = z + (size_t)row * HID;

    for (int i = tid; i < HID; i += 256) sv[i] = __float_as_uint(zr[i]);

    int k = g_keff;
    unsigned prefix = 0u;

#pragma unroll
    for (int shift = 24; shift >= 0; shift -= 8) {
        hist[tid] = 0;
        __syncthreads();
        const unsigned himask = (shift == 24) ? 0u : (0xffffffffu << (shift + 8));
        for (int i = tid; i < HID; i += 256) {
            unsigned v = sv[i];
            if ((v & himask) == prefix) atomicAdd(&hist[(v >> shift) & 255], 1);
        }
        __syncthreads();
        if (tid == 0) {
            int cum = 0, b = 255;
            for (;; --b) {
                cum += hist[b];
                if (cum >= k || b == 0) break;
            }
            sk = k - (cum - hist[b]);
            spre = prefix | ((unsigned)b << shift);
        }
        __syncthreads();
        k = sk;
        prefix = spre;
    }

    const float th = __uint_as_float(prefix);
    __half* zh = g_zh + (size_t)row * HID;
    for (int i = tid; i < HID; i += 256) {
        float v = __uint_as_float(sv[i]);
        v = (v >= th) ? v : 0.0f;
        zr[i] = v;
        zh[i] = __float2half_rn(v);
    }
}

// ---------------- launch ----------------
extern "C" void kernel_launch(void* const* d_in, const int* in_sizes, int n_in,
                              void* d_out, int out_size) {
    const float* x     = (const float*)d_in[0];
    const float* Ws    = (const float*)d_in[1];
    const float* bs    = (const float*)d_in[2];
    const float* Wr    = (const float*)d_in[3];
    const float* br    = (const float*)d_in[4];
    const float* W_enc = (const float*)d_in[5];
    const float* b_enc = (const float*)d_in[6];
    const float* W_dec = (const float*)d_in[7];
    const float* b_dec = (const float*)d_in[8];
    const int*   modep = (const int*)d_in[9];
    const int*   kptr  = (const int*)d_in[10];

    float* recon = (float*)d_out;
    float* z     = recon + (size_t)BB * IND;

    void *x0h, *x0l, *w1h, *w1l, *w2h, *w2l, *w3h, *xhh, *xhl, *zh, *pS0, *pS1;
    cudaGetSymbolAddress(&x0h, g_x0h); cudaGetSymbolAddress(&x0l, g_x0l);
    cudaGetSymbolAddress(&w1h, g_w1h); cudaGetSymbolAddress(&w1l, g_w1l);
    cudaGetSymbolAddress(&w2h, g_w2h); cudaGetSymbolAddress(&w2l, g_w2l);
    cudaGetSymbolAddress(&w3h, g_w3h);
    cudaGetSymbolAddress(&xhh, g_xhh); cudaGetSymbolAddress(&xhl, g_xhl);
    cudaGetSymbolAddress(&zh, g_zh);
    cudaGetSymbolAddress(&pS0, g_pS0); cudaGetSymbolAddress(&pS1, g_pS1);

    cudaFuncSetAttribute((const void*)gemm_m<1, true, false, false>,
                         cudaFuncAttributeMaxDynamicSharedMemorySize, DYN_SMEM);
    cudaFuncSetAttribute((const void*)gemm_m<2, false, false, true>,
                         cudaFuncAttributeMaxDynamicSharedMemorySize, DYN_SMEM);
    cudaFuncSetAttribute((const void*)gemm_m<0, false, true, false>,
                         cudaFuncAttributeMaxDynamicSharedMemorySize, DYN_SMEM);

    dim3 blk(256);

    split_w<<<((size_t)BB * SDIM / 4 + 255) / 256, blk>>>(x, nullptr, nullptr, (__half*)x0h, (__half*)x0l, BB * SDIM / 4);
    split_w<<<(SDIM * IND / 4 + 255) / 256, blk>>>(Ws, Wr, modep, (__half*)w1h, (__half*)w1l, SDIM * IND / 4);
    split_w<<<(IND * HID / 4 + 255) / 256, blk>>>(W_enc, nullptr, nullptr, (__half*)w2h, (__half*)w2l, IND * HID / 4);
    round_w<<<(HID * IND / 4 + 255) / 256, blk>>>(W_dec, (__half*)w3h, HID * IND / 4);

    // 1) xh = silu(x @ W_head + b_head) -> split halves   [fp16x3]
    gemm_m<1, true, false, false><<<dim3(IND / 128, BB / 128), blk, DYN_SMEM>>>(
        (const __half*)x0h, (const __half*)x0l, (const __half*)w1h, (const __half*)w1l,
        bs, br, modep, nullptr, (__half*)xhh, (__half*)xhl, nullptr, nullptr, IND, SDIM);

    // 2) h = relu(xh @ W_enc + b_enc) -> z region (fp32), fused entropy partials
    gemm_m<2, false, false, true><<<dim3(HID / 128, BB / 128), blk, DYN_SMEM>>>(
        (const __half*)xhh, (const __half*)xhl, (const __half*)w2h, (const __half*)w2l,
        b_enc, nullptr, nullptr, z, nullptr, nullptr, (float*)pS0, (float*)pS1, HID, IND);

    // 3) entropy finish, 4) k_eff, 5) k-WTA in place (+ fp16 copy of z)
    entfin_k<<<BB / 256, blk>>>();
    keff_k<<<1, blk>>>(kptr);
    kwta_k<<<BB, blk>>>(z);

    // 6) recon = z_sparse @ W_dec + b_dec   [single-pass fp16]
    gemm_m<0, false, true, false><<<dim3(IND / 128, BB / 128), blk, DYN_SMEM>>>(
        (const __half*)zh, nullptr, (const __half*)w3h, nullptr,
        b_dec, nullptr, nullptr, recon, nullptr, nullptr, nullptr, nullptr, IND, HID);
}

// round 17
// speedup vs baseline: 1.4953x; 1.0274x over previous
#include <cuda_runtime.h>
#include <cuda_fp16.h>
#include <math.h>
#include <stdint.h>

#define BB   8192
#define SDIM 1024
#define IND  512
#define HID  4096

#define LO_SCALE 2048.0f
#define LO_INV   (1.0f / 2048.0f)

// ---------------- scratch ----------------
__device__ __half g_x0h[(size_t)BB * SDIM], g_x0l[(size_t)BB * SDIM];
__device__ __half g_w1h[SDIM * IND], g_w1l[SDIM * IND];
__device__ __half g_w2h[IND * HID],  g_w2l[IND * HID];
__device__ __half g_w3h[HID * IND];
__device__ __half g_xhh[(size_t)BB * IND], g_xhl[(size_t)BB * IND];
__device__ __half g_zh[(size_t)BB * HID];
__device__ float  g_pS0[(size_t)BB * 32];
__device__ float  g_pS1[(size_t)BB * 32];
__device__ float  g_ent[BB];
__device__ int    g_keff;

// ---------------- helpers ----------------
__device__ __forceinline__ uint32_t smem_u32(const void* p) {
    uint32_t a;
    asm("{ .reg .u64 t; cvta.to.shared.u64 t, %1; cvt.u32.u64 %0, t; }" : "=r"(a) : "l"(p));
    return a;
}
// FMA-pipe exp: e^x = 2^(x*log2e), |rel err| ~2e-7
__device__ __forceinline__ float fexp(float x) {
    float t = fmaxf(x * 1.442695041f, -120.0f);
    t = fminf(t, 120.0f);
    float r = rintf(t);
    float f = t - r;
    float p = 1.5402e-4f;
    p = fmaf(p, f, 1.333558e-3f);
    p = fmaf(p, f, 9.618129e-3f);
    p = fmaf(p, f, 5.550411e-2f);
    p = fmaf(p, f, 2.402265e-1f);
    p = fmaf(p, f, 6.931472e-1f);
    p = fmaf(p, f, 1.0f);
    int i = (int)r;
    return p * __int_as_float((i + 127) << 23);
}
__device__ __forceinline__ void split_sc(float a, __half& h, __half& l) {
    h = __float2half_rn(a);
    l = __float2half_rn((a - __half2float(h)) * LO_SCALE);
}
__device__ __forceinline__ void split2_sc(float a, float b, uint32_t& H, uint32_t& L) {
    __half ha, la, hb, lb;
    split_sc(a, ha, la);
    split_sc(b, hb, lb);
    __half2 Hh = __halves2half2(ha, hb), Ll = __halves2half2(la, lb);
    H = *reinterpret_cast<uint32_t*>(&Hh);
    L = *reinterpret_cast<uint32_t*>(&Ll);
}
__device__ __forceinline__ void ldsm4(uint32_t* r, uint32_t addr) {
    asm volatile("ldmatrix.sync.aligned.m8n8.x4.shared.b16 {%0,%1,%2,%3}, [%4];"
        : "=r"(r[0]), "=r"(r[1]), "=r"(r[2]), "=r"(r[3]) : "r"(addr));
}
__device__ __forceinline__ void ldsm4t(uint32_t* r, uint32_t addr) {
    asm volatile("ldmatrix.sync.aligned.m8n8.x4.trans.shared.b16 {%0,%1,%2,%3}, [%4];"
        : "=r"(r[0]), "=r"(r[1]), "=r"(r[2]), "=r"(r[3]) : "r"(addr));
}
__device__ __forceinline__ void mma16816(float* c, const uint32_t* a, uint32_t b0, uint32_t b1) {
    asm volatile(
        "mma.sync.aligned.m16n8k16.row.col.f32.f16.f16.f32 "
        "{%0,%1,%2,%3}, {%4,%5,%6,%7}, {%8,%9}, {%0,%1,%2,%3};"
        : "+f"(c[0]), "+f"(c[1]), "+f"(c[2]), "+f"(c[3])
        : "r"(a[0]), "r"(a[1]), "r"(a[2]), "r"(a[3]), "r"(b0), "r"(b1));
}
__device__ __forceinline__ void mma16816h(uint32_t* c, const uint32_t* a, uint32_t b0, uint32_t b1) {
    asm volatile(
        "mma.sync.aligned.m16n8k16.row.col.f16.f16.f16.f16 "
        "{%0,%1}, {%2,%3,%4,%5}, {%6,%7}, {%0,%1};"
        : "+r"(c[0]), "+r"(c[1])
        : "r"(a[0]), "r"(a[1]), "r"(a[2]), "r"(a[3]), "r"(b0), "r"(b1));
}
__device__ __forceinline__ void cp_async16(uint32_t dst, const void* src) {
    asm volatile("cp.async.cg.shared.global [%0], [%1], 16;" :: "r"(dst), "l"(src));
}
#define CP_COMMIT() asm volatile("cp.async.commit_group;" ::: "memory")
template <int N>
__device__ __forceinline__ void cp_wait() {
    asm volatile("cp.async.wait_group %0;" :: "n"(N) : "memory");
}

// 3-pass A chunk [128 m][32 k]: two 64B m-rows per 128B smem row, XOR swizzle.
__device__ __forceinline__ uint32_t offA32(int m, int seg) {
    return (uint32_t)((m >> 1) * 128 + (m & 1) * 64 + (((seg) ^ ((m >> 1) & 3)) << 4));
}
// SINGLE A chunk [128 m][64 k]: 128B rows, XOR swizzle; seg 0..7
__device__ __forceinline__ uint32_t offA64(int m, int seg) {
    return (uint32_t)(m * 128 + (((seg) ^ (m & 7)) << 4));
}
// B chunk [k][128 n] halfs, 256B rows
__device__ __forceinline__ uint32_t offB(int k, int ns) {
    return (uint32_t)(k * 256 + (((ns) ^ (k & 7)) << 4));
}

#define STAGE_BYTES 32768
#define DYN_SMEM (2 * STAGE_BYTES + 1024)

// 3-pass loader: k-chunk 32 — Ah 0 | Al 8K | Bh 16K | Bl 24K
__device__ __forceinline__ void load_chunk3(
    uint32_t st, const __half* __restrict__ Ah_g, const __half* __restrict__ Al_g,
    const __half* __restrict__ Bh_g, const __half* __restrict__ Bl_g,
    int tid, int by, int bx, int c, int N, int K) {
    const int ra = tid >> 1, sa0 = (tid & 1) * 2;
    const size_t arow = (size_t)(by * 128 + ra) * K + c * 32;
#pragma unroll
    for (int j = 0; j < 2; ++j) {
        const int seg = sa0 + j;
        const uint32_t d = offA32(ra, seg);
        cp_async16(st + d,        Ah_g + arow + seg * 8);
        cp_async16(st + 8192 + d, Al_g + arow + seg * 8);
    }
    const int kb = tid >> 3, ns0 = (tid & 7) * 2;
    const size_t brow = (size_t)(c * 32 + kb) * N + bx * 128;
#pragma unroll
    for (int j = 0; j < 2; ++j) {
        const int ns = ns0 + j;
        const uint32_t d = offB(kb, ns);
        cp_async16(st + 16384 + d, Bh_g + brow + ns * 8);
        cp_async16(st + 24576 + d, Bl_g + brow + ns * 8);
    }
}
// SINGLE loader: k-chunk 64 — Ah 0 (16K) | Bh 16K (16K)
__device__ __forceinline__ void load_chunk1(
    uint32_t st, const __half* __restrict__ Ah_g, const __half* __restrict__ Bh_g,
    int tid, int by, int bx, int c, int N, int K) {
    const int ra = tid >> 1, sa0 = (tid & 1) * 4;
    const size_t arow = (size_t)(by * 128 + ra) * K + c * 64;
#pragma unroll
    for (int j = 0; j < 4; ++j) {
        const int seg = sa0 + j;
        cp_async16(st + offA64(ra, seg), Ah_g + arow + seg * 8);
    }
    const int kb = tid >> 2, ns0 = (tid & 3) * 4;
    const size_t brow = (size_t)(c * 64 + kb) * N + bx * 128;
#pragma unroll
    for (int j = 0; j < 4; ++j) {
        const int ns = ns0 + j;
        cp_async16(st + 16384 + offB(kb, ns), Bh_g + brow + ns * 8);
    }
}

// ---------------- fp16(x3) HMMA GEMM, CTA 128x128, warp 64x32, occ 2 ----------------
template <int ACT, bool OUTHALF, bool SINGLE, bool ENT>
__global__ __launch_bounds__(256, 2)
void gemm_m(const __half* __restrict__ Ah_g, const __half* __restrict__ Al_g,
            const __half* __restrict__ Bh_g, const __half* __restrict__ Bl_g,
            const float* __restrict__ bias0, const float* __restrict__ bias1,
            const int* __restrict__ modep,
            float* __restrict__ C, __half* __restrict__ Ch, __half* __restrict__ Cl,
            float* __restrict__ pS0, float* __restrict__ pS1,
            int N, int K) {
    extern __shared__ char dsm_raw[];
    __shared__ float sBias[128];
    __shared__ float sS0[128], sS1[128];

    const float* bias = bias0;
    if (modep != nullptr && *modep != 0) bias = bias1;

    char* base = dsm_raw;
    {
        uintptr_t mis = ((uintptr_t)base) & 1023;
        base += (1024 - mis) & 1023;
    }
    const uint32_t SB = smem_u32(base);

    const int tid = threadIdx.x;
    const int lane = tid & 31;
    const int wid = tid >> 5;
    const int wm = wid & 1;
    const int wn = wid >> 1;
    const int bx = blockIdx.x, by = blockIdx.y;

    if (tid < 128) {
        sBias[tid] = bias[bx * 128 + tid];
        if (ENT) { sS0[tid] = 0.0f; sS1[tid] = 0.0f; }
    }

    float    acc_hh[4][4][4];
    uint32_t acc_mx[4][4][2];
#pragma unroll
    for (int i = 0; i < 4; ++i)
#pragma unroll
        for (int j = 0; j < 4; ++j) {
#pragma unroll
            for (int q = 0; q < 4; ++q) acc_hh[i][j][q] = 0.0f;
            acc_mx[i][j][0] = 0u; acc_mx[i][j][1] = 0u;
        }

    const int KCH = SINGLE ? 64 : 32;
    const int NC = K / KCH;
    const int NKS = SINGLE ? 4 : 2;

    if (SINGLE) load_chunk1(SB, Ah_g, Bh_g, tid, by, bx, 0, N, K);
    else        load_chunk3(SB, Ah_g, Al_g, Bh_g, Bl_g, tid, by, bx, 0, N, K);
    CP_COMMIT();

    for (int c = 0; c < NC; ++c) {
        const uint32_t st = SB + (uint32_t)(c & 1) * STAGE_BYTES;
        if (c + 1 < NC) {
            const uint32_t nx = SB + (uint32_t)((c + 1) & 1) * STAGE_BYTES;
            if (SINGLE) load_chunk1(nx, Ah_g, Bh_g, tid, by, bx, c + 1, N, K);
            else        load_chunk3(nx, Ah_g, Al_g, Bh_g, Bl_g, tid, by, bx, c + 1, N, K);
            CP_COMMIT();
            cp_wait<1>();
        } else {
            cp_wait<0>();
        }
        __syncthreads();

        const uint32_t sAh = st;
        const uint32_t sBh = st + 16384;
        const uint32_t sAl = st + 8192;
        const uint32_t sBl = st + 24576;
#pragma unroll
        for (int ks = 0; ks < NKS; ++ks) {
            const int arow = wm * 64 + (lane & 15);
            const int ags  = 2 * ks + (lane >> 4);
            const int bk   = ks * 16 + (lane & 15);
            const int bns  = wn * 4 + (lane >> 4);

            uint32_t afh[4][4], bfh[2][4];
#pragma unroll
            for (int mt = 0; mt < 4; ++mt) {
                const uint32_t ao = SINGLE ? offA64(arow + mt * 16, ags)
                                           : offA32(arow + mt * 16, ags);
                ldsm4(afh[mt], sAh + ao);
            }
#pragma unroll
            for (int p = 0; p < 2; ++p) ldsm4t(bfh[p], sBh + offB(bk, bns + 2 * p));

#pragma unroll
            for (int mt = 0; mt < 4; ++mt)
#pragma unroll
                for (int nt = 0; nt < 4; ++nt)
                    mma16816(acc_hh[mt][nt], afh[mt],
                             bfh[nt >> 1][(nt & 1) * 2], bfh[nt >> 1][(nt & 1) * 2 + 1]);

            if (!SINGLE) {
                {
                    uint32_t bfl[2][4];
#pragma unroll
                    for (int p = 0; p < 2; ++p) ldsm4t(bfl[p], sBl + offB(bk, bns + 2 * p));
#pragma unroll
                    for (int mt = 0; mt < 4; ++mt)
#pragma unroll
                        for (int nt = 0; nt < 4; ++nt)
                            mma16816h(acc_mx[mt][nt], afh[mt],
                                      bfl[nt >> 1][(nt & 1) * 2], bfl[nt >> 1][(nt & 1) * 2 + 1]);
                }
#pragma unroll
                for (int mh = 0; mh < 2; ++mh) {
                    uint32_t afl[2][4];
#pragma unroll
                    for (int m2 = 0; m2 < 2; ++m2)
                        ldsm4(afl[m2], sAl + offA32(arow + (2 * mh + m2) * 16, ags));
#pragma unroll
                    for (int m2 = 0; m2 < 2; ++m2)
#pragma unroll
                        for (int nt = 0; nt < 4; ++nt)
                            mma16816h(acc_mx[2 * mh + m2][nt], afl[m2],
                                      bfh[nt >> 1][(nt & 1) * 2], bfh[nt >> 1][(nt & 1) * 2 + 1]);
                }
            }
        }
        __syncthreads();
    }

    // ---- epilogue ----
    const int gid = lane >> 2, tig = lane & 3;
#pragma unroll
    for (int mt = 0; mt < 4; ++mt) {
        float s0a = 0.f, s1a = 0.f, s0b = 0.f, s1b = 0.f;
#pragma unroll
        for (int nt = 0; nt < 4; ++nt) {
            const int lcol = wn * 32 + nt * 8 + tig * 2;
            const int col = bx * 128 + lcol;
            const float b0 = sBias[lcol], b1 = sBias[lcol + 1];
            const int m0 = by * 128 + wm * 64 + mt * 16 + gid;
            float v0, v1, v2, v3;
            if (SINGLE) {
                v0 = acc_hh[mt][nt][0] + b0;
                v1 = acc_hh[mt][nt][1] + b1;
                v2 = acc_hh[mt][nt][2] + b0;
                v3 = acc_hh[mt][nt][3] + b1;
            } else {
                float2 f01 = __half22float2(*reinterpret_cast<__half2*>(&acc_mx[mt][nt][0]));
                float2 f23 = __half22float2(*reinterpret_cast<__half2*>(&acc_mx[mt][nt][1]));
                v0 = acc_hh[mt][nt][0] + f01.x * LO_INV + b0;
                v1 = acc_hh[mt][nt][1] + f01.y * LO_INV + b1;
                v2 = acc_hh[mt][nt][2] + f23.x * LO_INV + b0;
                v3 = acc_hh[mt][nt][3] + f23.y * LO_INV + b1;
            }
            if (ACT == 1) {
                v0 = v0 / (1.0f + expf(-v0)); v1 = v1 / (1.0f + expf(-v1));
                v2 = v2 / (1.0f + expf(-v2)); v3 = v3 / (1.0f + expf(-v3));
            }
            if (ACT == 2) {
                v0 = fmaxf(v0, 0.0f); v1 = fmaxf(v1, 0.0f);
                v2 = fmaxf(v2, 0.0f); v3 = fmaxf(v3, 0.0f);
            }
            if (ENT) {
                float e0 = fexp(v0), e1 = fexp(v1), e2 = fexp(v2), e3 = fexp(v3);
                s0a += e0 + e1; s1a += v0 * e0 + v1 * e1;
                s0b += e2 + e3; s1b += v2 * e2 + v3 * e3;
            }
            if (OUTHALF) {
                uint32_t H0, L0, H1, L1;
                split2_sc(v0, v1, H0, L0);
                split2_sc(v2, v3, H1, L1);
                *(uint32_t*)(Ch + (size_t)m0 * N + col)       = H0;
                *(uint32_t*)(Cl + (size_t)m0 * N + col)       = L0;
                *(uint32_t*)(Ch + (size_t)(m0 + 8) * N + col) = H1;
                *(uint32_t*)(Cl + (size_t)(m0 + 8) * N + col) = L1;
            } else {
                float2 a; a.x = v0; a.y = v1;
                float2 b; b.x = v2; b.y = v3;
                *(float2*)(C + (size_t)m0 * N + col)       = a;
                *(float2*)(C + (size_t)(m0 + 8) * N + col) = b;
            }
        }
        if (ENT) {
#pragma unroll
            for (int o = 1; o <= 2; o <<= 1) {
                s0a += __shfl_xor_sync(0xffffffffu, s0a, o);
                s1a += __shfl_xor_sync(0xffffffffu, s1a, o);
                s0b += __shfl_xor_sync(0xffffffffu, s0b, o);
                s1b += __shfl_xor_sync(0xffffffffu, s1b, o);
            }
            if (tig == 0) {
                const int rl = wm * 64 + mt * 16 + gid;
                atomicAdd(&sS0[rl], s0a);
                atomicAdd(&sS1[rl], s1a);
                atomicAdd(&sS0[rl + 8], s0b);
                atomicAdd(&sS1[rl + 8], s1b);
            }
        }
    }
    if (ENT) {
        __syncthreads();
        if (tid < 128) {
            const size_t m = (size_t)(by * 128 + tid);
            pS0[m * 32 + bx] = sS0[tid];
            pS1[m * 32 + bx] = sS1[tid];
        }
    }
}

// ---------------- split prep ----------------
__global__ __launch_bounds__(256)
void split_w(const float* __restrict__ s0, const float* __restrict__ s1,
             const int* __restrict__ modep,
             __half* __restrict__ h, __half* __restrict__ l, int n4) {
    const float* s = s0;
    if (modep != nullptr && *modep != 0) s = s1;
    int i = blockIdx.x * 256 + threadIdx.x;
    if (i < n4) {
        float4 f = ((const float4*)s)[i];
        uint2 H, L;
        split2_sc(f.x, f.y, H.x, L.x);
        split2_sc(f.z, f.w, H.y, L.y);
        ((uint2*)h)[i] = H;
        ((uint2*)l)[i] = L;
    }
}

// ---------------- round prep (hi only, for W_dec) ----------------
__global__ __launch_bounds__(256)
void round_w(const float* __restrict__ s, __half* __restrict__ h, int n4) {
    int i = blockIdx.x * 256 + threadIdx.x;
    if (i < n4) {
        float4 f = ((const float4*)s)[i];
        __half2 a = __floats2half2_rn(f.x, f.y);
        __half2 b = __floats2half2_rn(f.z, f.w);
        uint2 H;
        H.x = *reinterpret_cast<uint32_t*>(&a);
        H.y = *reinterpret_cast<uint32_t*>(&b);
        ((uint2*)h)[i] = H;
    }
}

// ---------------- entropy finish ----------------
__global__ __launch_bounds__(256)
void entfin_k() {
    const int row = blockIdx.x * 256 + threadIdx.x;
    if (row < BB) {
        const float4* p0 = (const float4*)&g_pS0[(size_t)row * 32];
        const float4* p1 = (const float4*)&g_pS1[(size_t)row * 32];
        float S0 = 0.f, S1 = 0.f;
#pragma unroll
        for (int i = 0; i < 8; ++i) {
            float4 a = p0[i], b = p1[i];
            S0 += (a.x + a.y) + (a.z + a.w);
            S1 += (b.x + b.y) + (b.z + b.w);
        }
        g_ent[row] = logf(S0) - S1 / S0;
    }
}

// ---------------- k_eff ----------------
__global__ __launch_bounds__(256)
void keff_k(const int* __restrict__ kptr) {
    __shared__ float r0[8];
    const int tid = threadIdx.x;
    float s = 0.f;
    for (int i = tid; i < BB; i += 256) s += g_ent[i];
#pragma unroll
    for (int o = 16; o; o >>= 1) s += __shfl_xor_sync(0xffffffffu, s, o);
    if ((tid & 31) == 0) r0[tid >> 5] = s;
    __syncthreads();
    if (tid == 0) {
        float t = 0.f;
#pragma unroll
        for (int i = 0; i < 8; ++i) t += r0[i];
        float mean = t / (float)BB;
        float val = (float)(*kptr) * (1.0f + 0.5f * mean / logf((float)HID));
        int ke = (int)floorf(val);
        if (ke > HID / 2) ke = HID / 2;
        if (ke < 1) ke = 1;
        g_keff = ke;
    }
}

// ---------------- k-WTA radix select (vectorized I/O) ----------------
__global__ __launch_bounds__(256)
void kwta_k(float* __restrict__ z) {
    __shared__ unsigned sv[HID];
    __shared__ int hist[256];
    __shared__ int sk;
    __shared__ unsigned spre;
    const int row = blockIdx.x, tid = threadIdx.x;
    float* zr = z + (size_t)row * HID;

    // vectorized load: 4096 / (256*4) = 4 uint4 per thread
#pragma unroll
    for (int t = 0; t < 4; ++t) {
        const int i = (tid + t * 256) * 4;
        *(uint4*)&sv[i] = *(const uint4*)&zr[i];
    }

    int k = g_keff;
    unsigned prefix = 0u;

#pragma unroll
    for (int shift = 24; shift >= 0; shift -= 8) {
        hist[tid] = 0;
        __syncthreads();
        const unsigned himask = (shift == 24) ? 0u : (0xffffffffu << (shift + 8));
        for (int i = tid; i < HID; i += 256) {
            unsigned v = sv[i];
            if ((v & himask) == prefix) atomicAdd(&hist[(v >> shift) & 255], 1);
        }
        __syncthreads();
        if (tid == 0) {
            int cum = 0, b = 255;
            for (;; --b) {
                cum += hist[b];
                if (cum >= k || b == 0) break;
            }
            sk = k - (cum - hist[b]);
            spre = prefix | ((unsigned)b << shift);
        }
        __syncthreads();
        k = sk;
        prefix = spre;
    }

    const float th = __uint_as_float(prefix);
    __half* zh = g_zh + (size_t)row * HID;
#pragma unroll
    for (int t = 0; t < 4; ++t) {
        const int i = (tid + t * 256) * 4;
        uint4 u = *(const uint4*)&sv[i];
        float4 f;
        f.x = __uint_as_float(u.x); f.x = (f.x >= th) ? f.x : 0.0f;
        f.y = __uint_as_float(u.y); f.y = (f.y >= th) ? f.y : 0.0f;
        f.z = __uint_as_float(u.z); f.z = (f.z >= th) ? f.z : 0.0f;
        f.w = __uint_as_float(u.w); f.w = (f.w >= th) ? f.w : 0.0f;
        *(float4*)&zr[i] = f;
        __half2 h01 = __floats2half2_rn(f.x, f.y);
        __half2 h23 = __floats2half2_rn(f.z, f.w);
        uint2 hh;
        hh.x = *reinterpret_cast<uint32_t*>(&h01);
        hh.y = *reinterpret_cast<uint32_t*>(&h23);
        *(uint2*)&zh[i] = hh;
    }
}

// ---------------- launch ----------------
extern "C" void kernel_launch(void* const* d_in, const int* in_sizes, int n_in,
                              void* d_out, int out_size) {
    const float* x     = (const float*)d_in[0];
    const float* Ws    = (const float*)d_in[1];
    const float* bs    = (const float*)d_in[2];
    const float* Wr    = (const float*)d_in[3];
    const float* br    = (const float*)d_in[4];
    const float* W_enc = (const float*)d_in[5];
    const float* b_enc = (const float*)d_in[6];
    const float* W_dec = (const float*)d_in[7];
    const float* b_dec = (const float*)d_in[8];
    const int*   modep = (const int*)d_in[9];
    const int*   kptr  = (const int*)d_in[10];

    float* recon = (float*)d_out;
    float* z     = recon + (size_t)BB * IND;

    void *x0h, *x0l, *w1h, *w1l, *w2h, *w2l, *w3h, *xhh, *xhl, *zh, *pS0, *pS1;
    cudaGetSymbolAddress(&x0h, g_x0h); cudaGetSymbolAddress(&x0l, g_x0l);
    cudaGetSymbolAddress(&w1h, g_w1h); cudaGetSymbolAddress(&w1l, g_w1l);
    cudaGetSymbolAddress(&w2h, g_w2h); cudaGetSymbolAddress(&w2l, g_w2l);
    cudaGetSymbolAddress(&w3h, g_w3h);
    cudaGetSymbolAddress(&xhh, g_xhh); cudaGetSymbolAddress(&xhl, g_xhl);
    cudaGetSymbolAddress(&zh, g_zh);
    cudaGetSymbolAddress(&pS0, g_pS0); cudaGetSymbolAddress(&pS1, g_pS1);

    cudaFuncSetAttribute((const void*)gemm_m<1, true, false, false>,
                         cudaFuncAttributeMaxDynamicSharedMemorySize, DYN_SMEM);
    cudaFuncSetAttribute((const void*)gemm_m<2, false, false, true>,
                         cudaFuncAttributeMaxDynamicSharedMemorySize, DYN_SMEM);
    cudaFuncSetAttribute((const void*)gemm_m<0, false, true, false>,
                         cudaFuncAttributeMaxDynamicSharedMemorySize, DYN_SMEM);

    dim3 blk(256);

    split_w<<<((size_t)BB * SDIM / 4 + 255) / 256, blk>>>(x, nullptr, nullptr, (__half*)x0h, (__half*)x0l, BB * SDIM / 4);
    split_w<<<(SDIM * IND / 4 + 255) / 256, blk>>>(Ws, Wr, modep, (__half*)w1h, (__half*)w1l, SDIM * IND / 4);
    split_w<<<(IND * HID / 4 + 255) / 256, blk>>>(W_enc, nullptr, nullptr, (__half*)w2h, (__half*)w2l, IND * HID / 4);
    round_w<<<(HID * IND / 4 + 255) / 256, blk>>>(W_dec, (__half*)w3h, HID * IND / 4);

    // 1) xh = silu(x @ W_head + b_head) -> split halves   [fp16x3]
    gemm_m<1, true, false, false><<<dim3(IND / 128, BB / 128), blk, DYN_SMEM>>>(
        (const __half*)x0h, (const __half*)x0l, (const __half*)w1h, (const __half*)w1l,
        bs, br, modep, nullptr, (__half*)xhh, (__half*)xhl, nullptr, nullptr, IND, SDIM);

    // 2) h = relu(xh @ W_enc + b_enc) -> z region, fused entropy partials [fp16x3]
    gemm_m<2, false, false, true><<<dim3(HID / 128, BB / 128), blk, DYN_SMEM>>>(
        (const __half*)xhh, (const __half*)xhl, (const __half*)w2h, (const __half*)w2l,
        b_enc, nullptr, nullptr, z, nullptr, nullptr, (float*)pS0, (float*)pS1, HID, IND);

    // 3) entropy finish, 4) k_eff, 5) k-WTA in place (+ fp16 copy of z)
    entfin_k<<<BB / 256, blk>>>();
    keff_k<<<1, blk>>>(kptr);
    kwta_k<<<BB, blk>>>(z);

    // 6) recon = z_sparse @ W_dec + b_dec   [single-pass fp16, k-chunk 64]
    gemm_m<0, false, true, false><<<dim3(IND / 128, BB / 128), blk, DYN_SMEM>>>(
        (const __half*)zh, nullptr, (const __half*)w3h, nullptr,
        b_dec, nullptr, nullptr, recon, nullptr, nullptr, nullptr, nullptr, IND, HID);
}